// round 4
// baseline (speedup 1.0000x reference)
#include <cuda_runtime.h>
#include <cuda_bf16.h>
#include <math.h>

#define NN 50000
#define IN_DIM 256
#define HID 256
#define HEADS 4
#define C1 64
#define OUT_DIM 128
#define NEG_SLOPE 0.2f
#define EMAX_EDGES 850000   // E + N

// ---------------- scratch (device globals; no dynamic allocation) ----------------
// All vector-accessed arrays are 16B-aligned (float4/uint4/red.v4 requirement).
__device__ __align__(16) float    g_h1[NN * HID];          // x @ W1
__device__ __align__(16) float    g_out1[NN * HID];        // layer1 output
__device__ __align__(16) float    g_h2[NN * OUT_DIM];      // gelu(out1) @ W2
__device__ __align__(16) float    g_as1[NN * HEADS];
__device__ __align__(16) float    g_ad1[NN * HEADS];
__device__ __align__(16) unsigned g_emax1[NN * HEADS];
__device__ __align__(16) float    g_den1[NN * HEADS];
__device__ __align__(16) float    g_e1[EMAX_EDGES * HEADS];  // per-edge e, then ex
__device__ __align__(16) float    g_as2[NN];
__device__ __align__(16) float    g_ad2[NN];
__device__ __align__(16) unsigned g_emax2[NN];
__device__ __align__(16) float    g_den2[NN];
__device__ __align__(16) float    g_e2[EMAX_EDGES];

// ---------------- helpers ----------------
__device__ __forceinline__ unsigned fkey(float f) {
    unsigned u = __float_as_uint(f);
    return (u & 0x80000000u) ? ~u : (u | 0x80000000u);
}
__device__ __forceinline__ float fdec(unsigned k) {
    return __uint_as_float((k & 0x80000000u) ? (k ^ 0x80000000u) : ~k);
}
__device__ __forceinline__ void red_add_v4(float* addr, float4 v) {
    asm volatile("red.global.add.v4.f32 [%0], {%1,%2,%3,%4};"
                 :: "l"(addr), "f"(v.x), "f"(v.y), "f"(v.z), "f"(v.w)
                 : "memory");
}
__device__ __forceinline__ float lrelu(float v) {
    return v > 0.f ? v : NEG_SLOPE * v;
}

// ---------------- init: bias-broadcast outputs, zero accumulators ----------------
__global__ void init_kernel(const float* __restrict__ b1, const float* __restrict__ b2,
                            float* __restrict__ out) {
    int i = blockIdx.x * blockDim.x + threadIdx.x;
    if (i < NN * HID)    g_out1[i] = b1[i & (HID - 1)];
    if (i < NN * OUT_DIM) out[i] = b2[i & (OUT_DIM - 1)];
    if (i < NN * HEADS) { g_emax1[i] = 0u; g_den1[i] = 0.f; }
    if (i < NN)         { g_emax2[i] = 0u; g_den2[i] = 0.f; }
}

// ---------------- SGEMM: C[M,N] = A[M,K] @ B[K,N], row-major, fp32 ----------------
#define BM 128
#define BN 128
#define BKK 16
__global__ __launch_bounds__(256) void sgemm(int M, int N, int K,
                                             const float* __restrict__ A,
                                             const float* __restrict__ B,
                                             float* __restrict__ C) {
    __shared__ float As[BKK][BM];
    __shared__ float Bs[BKK][BN];
    int tid = threadIdx.x;
    int bx = blockIdx.x, by = blockIdx.y;
    int trow = tid >> 4;          // 0..15
    int tcol = tid & 15;          // 0..15

    float acc[8][8];
    #pragma unroll
    for (int i = 0; i < 8; i++)
        #pragma unroll
        for (int j = 0; j < 8; j++) acc[i][j] = 0.f;

    int aRow = tid >> 2;              // 0..63 (+64 for second)
    int aCol = (tid & 3) << 2;        // 0,4,8,12
    int bRow = tid >> 5;              // 0..7 (+8 for second)
    int bCol = (tid & 31) << 2;       // 0..124

    for (int k0 = 0; k0 < K; k0 += BKK) {
        #pragma unroll
        for (int r = 0; r < 2; r++) {
            int ar = aRow + 64 * r;
            int gr = by * BM + ar;
            float4 av = make_float4(0.f, 0.f, 0.f, 0.f);
            if (gr < M) av = *(const float4*)(A + (size_t)gr * K + k0 + aCol);
            As[aCol + 0][ar] = av.x; As[aCol + 1][ar] = av.y;
            As[aCol + 2][ar] = av.z; As[aCol + 3][ar] = av.w;

            int br = bRow + 8 * r;
            float4 bv = *(const float4*)(B + (size_t)(k0 + br) * N + bx * BN + bCol);
            *(float4*)&Bs[br][bCol] = bv;
        }
        __syncthreads();
        #pragma unroll
        for (int kk = 0; kk < BKK; kk++) {
            float ar8[8], br8[8];
            #pragma unroll
            for (int i = 0; i < 8; i++) ar8[i] = As[kk][trow * 8 + i];
            #pragma unroll
            for (int j = 0; j < 8; j++) br8[j] = Bs[kk][tcol * 8 + j];
            #pragma unroll
            for (int i = 0; i < 8; i++)
                #pragma unroll
                for (int j = 0; j < 8; j++) acc[i][j] = fmaf(ar8[i], br8[j], acc[i][j]);
        }
        __syncthreads();
    }
    #pragma unroll
    for (int i = 0; i < 8; i++) {
        int gr = by * BM + trow * 8 + i;
        if (gr < M) {
            float* cp = C + (size_t)gr * N + bx * BN + tcol * 8;
            *(float4*)cp = make_float4(acc[i][0], acc[i][1], acc[i][2], acc[i][3]);
            *(float4*)(cp + 4) = make_float4(acc[i][4], acc[i][5], acc[i][6], acc[i][7]);
        }
    }
}

// ---------------- layer-1 per-node attention dots: warp per node ----------------
__global__ void alpha1_kernel(const float* __restrict__ att_s, const float* __restrict__ att_d) {
    int w = (blockIdx.x * blockDim.x + threadIdx.x) >> 5;
    int lane = threadIdx.x & 31;
    if (w >= NN) return;
    const float4* hp = (const float4*)(g_h1 + (size_t)w * HID);
    const float4* sp = (const float4*)att_s;
    const float4* dp = (const float4*)att_d;
    float ps = 0.f, pd = 0.f;
    #pragma unroll
    for (int r = 0; r < 2; r++) {
        int i = 2 * lane + r;
        float4 v = hp[i], s = sp[i], d = dp[i];
        ps += v.x * s.x + v.y * s.y + v.z * s.z + v.w * s.w;
        pd += v.x * d.x + v.y * d.y + v.z * d.z + v.w * d.w;
    }
    // reduce within groups of 8 lanes (one head each)
    #pragma unroll
    for (int off = 4; off >= 1; off >>= 1) {
        ps += __shfl_xor_sync(0xffffffffu, ps, off);
        pd += __shfl_xor_sync(0xffffffffu, pd, off);
    }
    if ((lane & 7) == 0) {
        int h = lane >> 3;
        g_as1[w * HEADS + h] = ps;
        g_ad1[w * HEADS + h] = pd;
    }
}

// ---------------- layer-1 edge max ----------------
__global__ void edge_max1(const int* __restrict__ ei, int E, int EL) {
    int e = blockIdx.x * blockDim.x + threadIdx.x;
    if (e >= EL) return;
    int s, d;
    if (e < E) { s = ei[e]; d = ei[E + e]; } else { s = d = e - E; }
    float4 a = *(const float4*)(g_as1 + s * 4);
    float4 b = *(const float4*)(g_ad1 + d * 4);
    float v0 = lrelu(a.x + b.x), v1 = lrelu(a.y + b.y);
    float v2 = lrelu(a.z + b.z), v3 = lrelu(a.w + b.w);
    *(float4*)(g_e1 + (size_t)e * 4) = make_float4(v0, v1, v2, v3);
    atomicMax(&g_emax1[d * 4 + 0], fkey(v0));
    atomicMax(&g_emax1[d * 4 + 1], fkey(v1));
    atomicMax(&g_emax1[d * 4 + 2], fkey(v2));
    atomicMax(&g_emax1[d * 4 + 3], fkey(v3));
}

// ---------------- layer-1 edge exp + denom ----------------
__global__ void edge_exp1(const int* __restrict__ ei, int E, int EL) {
    int e = blockIdx.x * blockDim.x + threadIdx.x;
    if (e >= EL) return;
    int d;
    if (e < E) d = ei[E + e]; else d = e - E;
    float4 v = *(float4*)(g_e1 + (size_t)e * 4);
    uint4 k = *(uint4*)(g_emax1 + d * 4);
    float4 ex;
    ex.x = expf(v.x - fdec(k.x));
    ex.y = expf(v.y - fdec(k.y));
    ex.z = expf(v.z - fdec(k.z));
    ex.w = expf(v.w - fdec(k.w));
    *(float4*)(g_e1 + (size_t)e * 4) = ex;
    red_add_v4(g_den1 + d * 4, ex);
}

// ---------------- layer-1 aggregation: warp per edge, vector red ----------------
__global__ void aggregate1(const int* __restrict__ ei, int E, int EL) {
    int w = (blockIdx.x * blockDim.x + threadIdx.x) >> 5;
    int lane = threadIdx.x & 31;
    if (w >= EL) return;
    int s, d;
    if (w < E) { s = ei[w]; d = ei[E + w]; } else { s = d = w - E; }
    float aval = 0.f;
    if (lane < 4) aval = g_e1[(size_t)w * 4 + lane] / (g_den1[d * 4 + lane] + 1e-16f);
    float al[4];
    #pragma unroll
    for (int h = 0; h < 4; h++) al[h] = __shfl_sync(0xffffffffu, aval, h);
    const float4* hp = (const float4*)(g_h1 + (size_t)s * HID);
    float* op = g_out1 + (size_t)d * HID;
    #pragma unroll
    for (int r = 0; r < 2; r++) {
        int i = lane + 32 * r;          // float4 index in [0,64); head = i>>4
        float a = al[i >> 4];
        float4 v = hp[i];
        v.x *= a; v.y *= a; v.z *= a; v.w *= a;
        red_add_v4(op + i * 4, v);
    }
}

// ---------------- GELU (exact erf) in place on g_out1 ----------------
__global__ void gelu_kernel() {
    int i = blockIdx.x * blockDim.x + threadIdx.x;
    if (i >= NN * HID) return;
    float x = g_out1[i];
    g_out1[i] = 0.5f * x * (1.0f + erff(x * 0.70710678118654752f));
}

// ---------------- layer-2 per-node dots: warp per node ----------------
__global__ void alpha2_kernel(const float* __restrict__ att_s, const float* __restrict__ att_d) {
    int w = (blockIdx.x * blockDim.x + threadIdx.x) >> 5;
    int lane = threadIdx.x & 31;
    if (w >= NN) return;
    const float4* hp = (const float4*)(g_h2 + (size_t)w * OUT_DIM);
    float4 v = hp[lane];
    float4 s = ((const float4*)att_s)[lane];
    float4 d = ((const float4*)att_d)[lane];
    float ps = v.x * s.x + v.y * s.y + v.z * s.z + v.w * s.w;
    float pd = v.x * d.x + v.y * d.y + v.z * d.z + v.w * d.w;
    #pragma unroll
    for (int off = 16; off >= 1; off >>= 1) {
        ps += __shfl_xor_sync(0xffffffffu, ps, off);
        pd += __shfl_xor_sync(0xffffffffu, pd, off);
    }
    if (lane == 0) { g_as2[w] = ps; g_ad2[w] = pd; }
}

// ---------------- layer-2 edge max ----------------
__global__ void edge_max2(const int* __restrict__ ei, int E, int EL) {
    int e = blockIdx.x * blockDim.x + threadIdx.x;
    if (e >= EL) return;
    int s, d;
    if (e < E) { s = ei[e]; d = ei[E + e]; } else { s = d = e - E; }
    float v = lrelu(g_as2[s] + g_ad2[d]);
    g_e2[e] = v;
    atomicMax(&g_emax2[d], fkey(v));
}

// ---------------- layer-2 edge exp + denom ----------------
__global__ void edge_exp2(const int* __restrict__ ei, int E, int EL) {
    int e = blockIdx.x * blockDim.x + threadIdx.x;
    if (e >= EL) return;
    int d;
    if (e < E) d = ei[E + e]; else d = e - E;
    float ex = expf(g_e2[e] - fdec(g_emax2[d]));
    g_e2[e] = ex;
    atomicAdd(&g_den2[d], ex);
}

// ---------------- layer-2 aggregation: warp per edge into d_out ----------------
__global__ void aggregate2(const int* __restrict__ ei, int E, int EL,
                           float* __restrict__ out) {
    int w = (blockIdx.x * blockDim.x + threadIdx.x) >> 5;
    int lane = threadIdx.x & 31;
    if (w >= EL) return;
    int s, d;
    if (w < E) { s = ei[w]; d = ei[E + w]; } else { s = d = w - E; }
    float a = g_e2[w] / (g_den2[d] + 1e-16f);
    float4 v = ((const float4*)(g_h2 + (size_t)s * OUT_DIM))[lane];
    v.x *= a; v.y *= a; v.z *= a; v.w *= a;
    red_add_v4(out + (size_t)d * OUT_DIM + lane * 4, v);
}

// ---------------- launch ----------------
extern "C" void kernel_launch(void* const* d_in, const int* in_sizes, int n_in,
                              void* d_out, int out_size) {
    const float* x = (const float*)d_in[0];
    const int* ei = (const int*)d_in[1];        // int32: JAX x64 disabled -> int64 request yields int32
    const float* W1 = (const float*)d_in[2];
    const float* att_src1 = (const float*)d_in[3];
    const float* att_dst1 = (const float*)d_in[4];
    const float* bias1 = (const float*)d_in[5];
    const float* W2 = (const float*)d_in[6];
    const float* att_src2 = (const float*)d_in[7];
    const float* att_dst2 = (const float*)d_in[8];
    const float* bias2 = (const float*)d_in[9];
    float* out = (float*)d_out;

    int E = in_sizes[1] / 2;
    int EL = E + NN;

    float* h1;   cudaGetSymbolAddress((void**)&h1, g_h1);
    float* out1; cudaGetSymbolAddress((void**)&out1, g_out1);
    float* h2;   cudaGetSymbolAddress((void**)&h2, g_h2);

    const int T = 256;
    // 1. init outputs with biases, clear accumulators
    init_kernel<<<(NN * HID + T - 1) / T, T>>>(bias1, bias2, out);
    // 2. h1 = x @ W1
    {
        dim3 g(HID / BN, (NN + BM - 1) / BM);
        sgemm<<<g, T>>>(NN, HID, IN_DIM, x, W1, h1);
    }
    // 3. per-node attention coefficients
    alpha1_kernel<<<(NN * 32 + T - 1) / T, T>>>(att_src1, att_dst1);
    // 4-6. edge softmax + aggregation
    int eb = (EL + T - 1) / T;
    edge_max1<<<eb, T>>>(ei, E, EL);
    edge_exp1<<<eb, T>>>(ei, E, EL);
    aggregate1<<<(EL * 32 + T - 1) / T, T>>>(ei, E, EL);
    // 7. gelu in place
    gelu_kernel<<<(NN * HID + T - 1) / T, T>>>();
    // 8. h2 = gelu(out1) @ W2
    {
        dim3 g(OUT_DIM / BN, (NN + BM - 1) / BM);
        sgemm<<<g, T>>>(NN, OUT_DIM, HID, out1, W2, h2);
    }
    // 9. layer-2 attention coefficients
    alpha2_kernel<<<(NN * 32 + T - 1) / T, T>>>(att_src2, att_dst2);
    // 10-12. layer-2 edge softmax + aggregation into d_out
    edge_max2<<<eb, T>>>(ei, E, EL);
    edge_exp2<<<eb, T>>>(ei, E, EL);
    aggregate2<<<(EL * 32 + T - 1) / T, T>>>(ei, E, EL, out);
}

// round 6
// speedup vs baseline: 1.4826x; 1.4826x over previous
#include <cuda_runtime.h>
#include <math.h>

#define NN 50000
#define IN_DIM 256
#define HID 256
#define HEADS 4
#define OUT_DIM 128
#define NEG_SLOPE 0.2f
#define EMAXE 850000   // E + N

// ---------------- scratch (device globals) ----------------
__device__ __align__(16) float g_h1[NN * HID];       // x @ W1
__device__ __align__(16) float g_out1[NN * HID];     // layer-1 output (post-gelu)
__device__ __align__(16) float g_h2[NN * OUT_DIM];   // out1 @ W2
__device__ __align__(16) float g_as1[NN * HEADS];
__device__ __align__(16) float g_ad1[NN * HEADS];
__device__ float g_as2[NN];
__device__ float g_ad2[NN];
// CSR (by destination), rebuilt every launch
__device__ int g_deg[NN];
__device__ int g_row_ptr[NN + 1];
__device__ int g_cursor[NN];
__device__ int g_csr_src[EMAXE];

__device__ __forceinline__ float lrelu(float v) {
    return v > 0.f ? v : NEG_SLOPE * v;
}
#define NEG_INF __int_as_float(0xff800000)

// ---------------- CSR build ----------------
__global__ void init_deg() {
    int i = blockIdx.x * blockDim.x + threadIdx.x;
    if (i < NN) g_deg[i] = 1;               // self-loop pre-counted
}
__global__ void add_deg(const int* __restrict__ ei, int E) {
    int e = blockIdx.x * blockDim.x + threadIdx.x;
    if (e < E) atomicAdd(&g_deg[ei[E + e]], 1);
}
// single-block exclusive scan over g_deg -> g_row_ptr, g_cursor
__global__ __launch_bounds__(1024) void scan_deg(int n) {
    __shared__ int warp_sums[32];
    __shared__ int s_carry;
    int tid = threadIdx.x, lane = tid & 31, wid = tid >> 5;
    if (tid == 0) s_carry = 0;
    __syncthreads();
    for (int base = 0; base < n; base += 1024) {
        int i = base + tid;
        int v = (i < n) ? g_deg[i] : 0;
        int x = v;
        #pragma unroll
        for (int off = 1; off < 32; off <<= 1) {
            int y = __shfl_up_sync(0xffffffffu, x, off);
            if (lane >= off) x += y;
        }
        if (lane == 31) warp_sums[wid] = x;
        __syncthreads();
        if (wid == 0) {
            int wv = warp_sums[lane];
            #pragma unroll
            for (int off = 1; off < 32; off <<= 1) {
                int y = __shfl_up_sync(0xffffffffu, wv, off);
                if (lane >= off) wv += y;
            }
            warp_sums[lane] = wv;
        }
        __syncthreads();
        int warp_off = (wid > 0) ? warp_sums[wid - 1] : 0;
        int incl = x + warp_off + s_carry;
        int excl = incl - v;
        if (i < n) { g_row_ptr[i] = excl; g_cursor[i] = excl; }
        __syncthreads();
        if (tid == 1023) s_carry = incl;
        __syncthreads();
    }
    if (threadIdx.x == 0) g_row_ptr[n] = s_carry;
}
__global__ void fill_csr(const int* __restrict__ ei, int E, int EL) {
    int e = blockIdx.x * blockDim.x + threadIdx.x;
    if (e >= EL) return;
    int s, d;
    if (e < E) { s = ei[e]; d = ei[E + e]; } else { s = d = e - E; }
    int pos = atomicAdd(&g_cursor[d], 1);
    g_csr_src[pos] = s;
}

// ---------------- SGEMM: C[M,N] = A[M,K] @ B[K,N], fp32 ----------------
#define BM 128
#define BN 128
#define BKK 16
__global__ __launch_bounds__(256) void sgemm(int M, int N, int K,
                                             const float* __restrict__ A,
                                             const float* __restrict__ B,
                                             float* __restrict__ C) {
    __shared__ float As[BKK][BM];
    __shared__ float Bs[BKK][BN];
    int tid = threadIdx.x;
    int bx = blockIdx.x, by = blockIdx.y;
    int trow = tid >> 4;
    int tcol = tid & 15;

    float acc[8][8];
    #pragma unroll
    for (int i = 0; i < 8; i++)
        #pragma unroll
        for (int j = 0; j < 8; j++) acc[i][j] = 0.f;

    int aRow = tid >> 2;
    int aCol = (tid & 3) << 2;
    int bRow = tid >> 5;
    int bCol = (tid & 31) << 2;

    for (int k0 = 0; k0 < K; k0 += BKK) {
        #pragma unroll
        for (int r = 0; r < 2; r++) {
            int ar = aRow + 64 * r;
            int gr = by * BM + ar;
            float4 av = make_float4(0.f, 0.f, 0.f, 0.f);
            if (gr < M) av = *(const float4*)(A + (size_t)gr * K + k0 + aCol);
            As[aCol + 0][ar] = av.x; As[aCol + 1][ar] = av.y;
            As[aCol + 2][ar] = av.z; As[aCol + 3][ar] = av.w;

            int br = bRow + 8 * r;
            float4 bv = *(const float4*)(B + (size_t)(k0 + br) * N + bx * BN + bCol);
            *(float4*)&Bs[br][bCol] = bv;
        }
        __syncthreads();
        #pragma unroll
        for (int kk = 0; kk < BKK; kk++) {
            float ar8[8], br8[8];
            #pragma unroll
            for (int i = 0; i < 8; i++) ar8[i] = As[kk][trow * 8 + i];
            #pragma unroll
            for (int j = 0; j < 8; j++) br8[j] = Bs[kk][tcol * 8 + j];
            #pragma unroll
            for (int i = 0; i < 8; i++)
                #pragma unroll
                for (int j = 0; j < 8; j++) acc[i][j] = fmaf(ar8[i], br8[j], acc[i][j]);
        }
        __syncthreads();
    }
    #pragma unroll
    for (int i = 0; i < 8; i++) {
        int gr = by * BM + trow * 8 + i;
        if (gr < M) {
            float* cp = C + (size_t)gr * N + bx * BN + tcol * 8;
            *(float4*)cp = make_float4(acc[i][0], acc[i][1], acc[i][2], acc[i][3]);
            *(float4*)(cp + 4) = make_float4(acc[i][4], acc[i][5], acc[i][6], acc[i][7]);
        }
    }
}

// ---------------- per-node attention dots ----------------
__global__ void alpha1_kernel(const float* __restrict__ att_s, const float* __restrict__ att_d) {
    int w = (blockIdx.x * blockDim.x + threadIdx.x) >> 5;
    int lane = threadIdx.x & 31;
    if (w >= NN) return;
    const float4* hp = (const float4*)(g_h1 + (size_t)w * HID);
    const float4* sp = (const float4*)att_s;
    const float4* dp = (const float4*)att_d;
    float ps = 0.f, pd = 0.f;
    #pragma unroll
    for (int r = 0; r < 2; r++) {
        int i = 2 * lane + r;
        float4 v = hp[i], s = sp[i], d = dp[i];
        ps += v.x * s.x + v.y * s.y + v.z * s.z + v.w * s.w;
        pd += v.x * d.x + v.y * d.y + v.z * d.z + v.w * d.w;
    }
    #pragma unroll
    for (int off = 4; off >= 1; off >>= 1) {
        ps += __shfl_xor_sync(0xffffffffu, ps, off);
        pd += __shfl_xor_sync(0xffffffffu, pd, off);
    }
    if ((lane & 7) == 0) {
        int h = lane >> 3;
        g_as1[w * HEADS + h] = ps;
        g_ad1[w * HEADS + h] = pd;
    }
}

__global__ void alpha2_kernel(const float* __restrict__ att_s, const float* __restrict__ att_d) {
    int w = (blockIdx.x * blockDim.x + threadIdx.x) >> 5;
    int lane = threadIdx.x & 31;
    if (w >= NN) return;
    const float4* hp = (const float4*)(g_h2 + (size_t)w * OUT_DIM);
    float4 v = hp[lane];
    float4 s = ((const float4*)att_s)[lane];
    float4 d = ((const float4*)att_d)[lane];
    float ps = v.x * s.x + v.y * s.y + v.z * s.z + v.w * s.w;
    float pd = v.x * d.x + v.y * d.y + v.z * d.z + v.w * d.w;
    #pragma unroll
    for (int off = 16; off >= 1; off >>= 1) {
        ps += __shfl_xor_sync(0xffffffffu, ps, off);
        pd += __shfl_xor_sync(0xffffffffu, pd, off);
    }
    if (lane == 0) { g_as2[w] = ps; g_ad2[w] = pd; }
}

// ---------------- fused layer-1: softmax + aggregate + bias + gelu ----------------
// one warp per destination node; lane holds float4 chunks i=lane and i=lane+32
__global__ __launch_bounds__(256) void fused_layer1(const float* __restrict__ bias1) {
    int d = (blockIdx.x * blockDim.x + threadIdx.x) >> 5;
    int lane = threadIdx.x & 31;
    if (d >= NN) return;
    int rp = g_row_ptr[d], rp1 = g_row_ptr[d + 1];
    float4 adv = *(const float4*)(g_ad1 + d * 4);

    // pass A: per-head max over edges (lanes split edges)
    float4 m = make_float4(NEG_INF, NEG_INF, NEG_INF, NEG_INF);
    for (int j = rp + lane; j < rp1; j += 32) {
        int s = g_csr_src[j];
        float4 av = *(const float4*)(g_as1 + s * 4);
        m.x = fmaxf(m.x, lrelu(av.x + adv.x));
        m.y = fmaxf(m.y, lrelu(av.y + adv.y));
        m.z = fmaxf(m.z, lrelu(av.z + adv.z));
        m.w = fmaxf(m.w, lrelu(av.w + adv.w));
    }
    #pragma unroll
    for (int off = 16; off >= 1; off >>= 1) {
        m.x = fmaxf(m.x, __shfl_xor_sync(0xffffffffu, m.x, off));
        m.y = fmaxf(m.y, __shfl_xor_sync(0xffffffffu, m.y, off));
        m.z = fmaxf(m.z, __shfl_xor_sync(0xffffffffu, m.z, off));
        m.w = fmaxf(m.w, __shfl_xor_sync(0xffffffffu, m.w, off));
    }

    // pass B: per-head exp-sum
    float4 den = make_float4(0.f, 0.f, 0.f, 0.f);
    for (int j = rp + lane; j < rp1; j += 32) {
        int s = g_csr_src[j];
        float4 av = *(const float4*)(g_as1 + s * 4);
        den.x += __expf(lrelu(av.x + adv.x) - m.x);
        den.y += __expf(lrelu(av.y + adv.y) - m.y);
        den.z += __expf(lrelu(av.z + adv.z) - m.z);
        den.w += __expf(lrelu(av.w + adv.w) - m.w);
    }
    #pragma unroll
    for (int off = 16; off >= 1; off >>= 1) {
        den.x += __shfl_xor_sync(0xffffffffu, den.x, off);
        den.y += __shfl_xor_sync(0xffffffffu, den.y, off);
        den.z += __shfl_xor_sync(0xffffffffu, den.z, off);
        den.w += __shfl_xor_sync(0xffffffffu, den.w, off);
    }
    float4 inv = make_float4(1.f / (den.x + 1e-16f), 1.f / (den.y + 1e-16f),
                             1.f / (den.z + 1e-16f), 1.f / (den.w + 1e-16f));

    // lane's two heads: ha = (lane>>4)&1 in {0,1}, hb = ha+2
    int hsel = (lane >> 4) & 1;
    float ma  = hsel ? m.y   : m.x,   mb  = hsel ? m.w   : m.z;
    float ia  = hsel ? inv.y : inv.x, ib  = hsel ? inv.w : inv.z;
    float ada = hsel ? adv.y : adv.x, adb = hsel ? adv.w : adv.z;

    // pass C: whole warp per edge, accumulate in registers
    float4 acc0 = make_float4(0.f, 0.f, 0.f, 0.f);
    float4 acc1 = make_float4(0.f, 0.f, 0.f, 0.f);
    for (int j = rp; j < rp1; j++) {
        int s = g_csr_src[j];
        float4 av = *(const float4*)(g_as1 + s * 4);
        float asa = hsel ? av.y : av.x;
        float asb = hsel ? av.w : av.z;
        float aa = __expf(lrelu(asa + ada) - ma) * ia;
        float ab = __expf(lrelu(asb + adb) - mb) * ib;
        const float4* hp = (const float4*)(g_h1 + (size_t)s * HID);
        float4 v0 = hp[lane];
        float4 v1 = hp[lane + 32];
        acc0.x += aa * v0.x; acc0.y += aa * v0.y; acc0.z += aa * v0.z; acc0.w += aa * v0.w;
        acc1.x += ab * v1.x; acc1.y += ab * v1.y; acc1.z += ab * v1.z; acc1.w += ab * v1.w;
    }

    // epilogue: bias + exact gelu, single write
    float4 b0 = ((const float4*)bias1)[lane];
    float4 b1 = ((const float4*)bias1)[lane + 32];
    acc0.x += b0.x; acc0.y += b0.y; acc0.z += b0.z; acc0.w += b0.w;
    acc1.x += b1.x; acc1.y += b1.y; acc1.z += b1.z; acc1.w += b1.w;
    const float kI = 0.70710678118654752f;
    acc0.x = 0.5f * acc0.x * (1.f + erff(acc0.x * kI));
    acc0.y = 0.5f * acc0.y * (1.f + erff(acc0.y * kI));
    acc0.z = 0.5f * acc0.z * (1.f + erff(acc0.z * kI));
    acc0.w = 0.5f * acc0.w * (1.f + erff(acc0.w * kI));
    acc1.x = 0.5f * acc1.x * (1.f + erff(acc1.x * kI));
    acc1.y = 0.5f * acc1.y * (1.f + erff(acc1.y * kI));
    acc1.z = 0.5f * acc1.z * (1.f + erff(acc1.z * kI));
    acc1.w = 0.5f * acc1.w * (1.f + erff(acc1.w * kI));
    float4* op = (float4*)(g_out1 + (size_t)d * HID);
    op[lane] = acc0;
    op[lane + 32] = acc1;
}

// ---------------- fused layer-2: softmax + aggregate + bias -> d_out ----------------
__global__ __launch_bounds__(256) void fused_layer2(const float* __restrict__ bias2,
                                                    float* __restrict__ out) {
    int d = (blockIdx.x * blockDim.x + threadIdx.x) >> 5;
    int lane = threadIdx.x & 31;
    if (d >= NN) return;
    int rp = g_row_ptr[d], rp1 = g_row_ptr[d + 1];
    float ad = g_ad2[d];

    float m = NEG_INF;
    for (int j = rp + lane; j < rp1; j += 32)
        m = fmaxf(m, lrelu(g_as2[g_csr_src[j]] + ad));
    #pragma unroll
    for (int off = 16; off >= 1; off >>= 1)
        m = fmaxf(m, __shfl_xor_sync(0xffffffffu, m, off));

    float den = 0.f;
    for (int j = rp + lane; j < rp1; j += 32)
        den += __expf(lrelu(g_as2[g_csr_src[j]] + ad) - m);
    #pragma unroll
    for (int off = 16; off >= 1; off >>= 1)
        den += __shfl_xor_sync(0xffffffffu, den, off);
    float inv = 1.f / (den + 1e-16f);

    float4 acc = make_float4(0.f, 0.f, 0.f, 0.f);
    for (int j = rp; j < rp1; j++) {
        int s = g_csr_src[j];
        float a = __expf(lrelu(g_as2[s] + ad) - m) * inv;
        float4 v = ((const float4*)(g_h2 + (size_t)s * OUT_DIM))[lane];
        acc.x += a * v.x; acc.y += a * v.y; acc.z += a * v.z; acc.w += a * v.w;
    }
    float4 b = ((const float4*)bias2)[lane];
    acc.x += b.x; acc.y += b.y; acc.z += b.z; acc.w += b.w;
    ((float4*)(out + (size_t)d * OUT_DIM))[lane] = acc;
}

// ---------------- launch ----------------
extern "C" void kernel_launch(void* const* d_in, const int* in_sizes, int n_in,
                              void* d_out, int out_size) {
    const float* x = (const float*)d_in[0];
    const int* ei = (const int*)d_in[1];        // int32 (JAX x64 disabled)
    const float* W1 = (const float*)d_in[2];
    const float* att_src1 = (const float*)d_in[3];
    const float* att_dst1 = (const float*)d_in[4];
    const float* bias1 = (const float*)d_in[5];
    const float* W2 = (const float*)d_in[6];
    const float* att_src2 = (const float*)d_in[7];
    const float* att_dst2 = (const float*)d_in[8];
    const float* bias2 = (const float*)d_in[9];
    float* out = (float*)d_out;

    int E = in_sizes[1] / 2;
    int EL = E + NN;

    float* h1;   cudaGetSymbolAddress((void**)&h1, g_h1);
    float* out1; cudaGetSymbolAddress((void**)&out1, g_out1);
    float* h2;   cudaGetSymbolAddress((void**)&h2, g_h2);

    const int T = 256;
    // CSR build (by destination)
    init_deg<<<(NN + T - 1) / T, T>>>();
    add_deg<<<(E + T - 1) / T, T>>>(ei, E);
    scan_deg<<<1, 1024>>>(NN);
    fill_csr<<<(EL + T - 1) / T, T>>>(ei, E, EL);
    // layer 1
    {
        dim3 g(HID / BN, (NN + BM - 1) / BM);
        sgemm<<<g, T>>>(NN, HID, IN_DIM, x, W1, h1);
    }
    alpha1_kernel<<<(NN * 32 + T - 1) / T, T>>>(att_src1, att_dst1);
    fused_layer1<<<(NN * 32 + T - 1) / T, T>>>(bias1);
    // layer 2
    {
        dim3 g(OUT_DIM / BN, (NN + BM - 1) / BM);
        sgemm<<<g, T>>>(NN, OUT_DIM, HID, out1, W2, h2);
    }
    alpha2_kernel<<<(NN * 32 + T - 1) / T, T>>>(att_src2, att_dst2);
    fused_layer2<<<(NN * 32 + T - 1) / T, T>>>(bias2, out);
}

// round 9
// speedup vs baseline: 1.6402x; 1.1063x over previous
#include <cuda_runtime.h>
#include <math.h>

#define NN 50000
#define IN_DIM 256
#define HID 256
#define HEADS 4
#define OUT_DIM 128
#define NEG_SLOPE 0.2f
#define EMAXE 850000   // E + N

// ---------------- scratch (device globals) ----------------
__device__ __align__(16) float g_h1[NN * HID];       // x @ W1
__device__ __align__(16) float g_out1[NN * HID];     // layer-1 output (post-gelu)
__device__ __align__(16) float g_h2[NN * OUT_DIM];   // out1 @ W2
__device__ __align__(16) float g_as1[NN * HEADS];
__device__ __align__(16) float g_ad1[NN * HEADS];
__device__ float g_as2[NN];
__device__ float g_ad2[NN];
// CSR (by destination), rebuilt every launch
__device__ int g_deg[NN];
__device__ int g_row_ptr[NN + 1];
__device__ int g_cursor[NN];
__device__ int g_csr_src[EMAXE];

__device__ __forceinline__ float lrelu(float v) {
    return v > 0.f ? v : NEG_SLOPE * v;
}
#define NEG_INF __int_as_float(0xff800000)

// ---------------- CSR build ----------------
__global__ void init_deg() {
    int i = blockIdx.x * blockDim.x + threadIdx.x;
    if (i < NN) g_deg[i] = 1;               // self-loop pre-counted
}
__global__ void add_deg(const int* __restrict__ ei, int E) {
    int e = blockIdx.x * blockDim.x + threadIdx.x;
    if (e < E) atomicAdd(&g_deg[ei[E + e]], 1);
}
__global__ __launch_bounds__(1024) void scan_deg(int n) {
    __shared__ int warp_sums[32];
    __shared__ int s_carry;
    int tid = threadIdx.x, lane = tid & 31, wid = tid >> 5;
    if (tid == 0) s_carry = 0;
    __syncthreads();
    for (int base = 0; base < n; base += 1024) {
        int i = base + tid;
        int v = (i < n) ? g_deg[i] : 0;
        int x = v;
        #pragma unroll
        for (int off = 1; off < 32; off <<= 1) {
            int y = __shfl_up_sync(0xffffffffu, x, off);
            if (lane >= off) x += y;
        }
        if (lane == 31) warp_sums[wid] = x;
        __syncthreads();
        if (wid == 0) {
            int wv = warp_sums[lane];
            #pragma unroll
            for (int off = 1; off < 32; off <<= 1) {
                int y = __shfl_up_sync(0xffffffffu, wv, off);
                if (lane >= off) wv += y;
            }
            warp_sums[lane] = wv;
        }
        __syncthreads();
        int warp_off = (wid > 0) ? warp_sums[wid - 1] : 0;
        int incl = x + warp_off + s_carry;
        int excl = incl - v;
        if (i < n) { g_row_ptr[i] = excl; g_cursor[i] = excl; }
        __syncthreads();
        if (tid == 1023) s_carry = incl;
        __syncthreads();
    }
    if (threadIdx.x == 0) g_row_ptr[n] = s_carry;
}
__global__ void fill_csr(const int* __restrict__ ei, int E, int EL) {
    int e = blockIdx.x * blockDim.x + threadIdx.x;
    if (e >= EL) return;
    int s, d;
    if (e < E) { s = ei[e]; d = ei[E + e]; } else { s = d = e - E; }
    int pos = atomicAdd(&g_cursor[d], 1);
    g_csr_src[pos] = s;
}

// ---------------- tf32 helpers ----------------
__device__ __forceinline__ float tf32_rna(float a) {
    unsigned r;
    asm("cvt.rna.tf32.f32 %0, %1;" : "=r"(r) : "f"(a));
    return __uint_as_float(r);
}
__device__ __forceinline__ void mma8(float* d, const float* a, const float* b) {
    asm volatile(
        "mma.sync.aligned.m16n8k8.row.col.f32.tf32.tf32.f32 "
        "{%0,%1,%2,%3}, {%4,%5,%6,%7}, {%8,%9}, {%0,%1,%2,%3};\n"
        : "+f"(d[0]), "+f"(d[1]), "+f"(d[2]), "+f"(d[3])
        : "r"(__float_as_uint(a[0])), "r"(__float_as_uint(a[1])),
          "r"(__float_as_uint(a[2])), "r"(__float_as_uint(a[3])),
          "r"(__float_as_uint(b[0])), "r"(__float_as_uint(b[1])));
}

// ---------------- tensor-core GEMM: C[M,N] = A[M,K] @ B[K,N] (3xTF32) ----------------
// block tile 128x128, BK=8, 256 threads (8 warps, 64x32 warp tiles), double-buffered
#define GBM 128
#define GBN 128
#define GBK 8
#define KSTR 136     // padded smem row stride (floats); bank = 8k+idx -> conflict-free

__global__ __launch_bounds__(256, 1) void gemm_tf32(int M, int N, int K,
                                                    const float* __restrict__ A,
                                                    const float* __restrict__ B,
                                                    float* __restrict__ C) {
    __shared__ __align__(16) float sAh[2][GBK][KSTR];
    __shared__ __align__(16) float sAl[2][GBK][KSTR];
    __shared__ __align__(16) float sBh[2][GBK][KSTR];
    __shared__ __align__(16) float sBl[2][GBK][KSTR];

    int tid = threadIdx.x;
    int lane = tid & 31, w = tid >> 5;
    int g = lane >> 2, tig = lane & 3;
    int warp_m = (w >> 2) * 64;     // 0 or 64
    int warp_n = (w & 3) * 32;      // 0,32,64,96
    int gm = blockIdx.y * GBM;
    int gn = blockIdx.x * GBN;

    // global staging addresses
    int aRow = tid >> 1;            // 0..127
    int aHalf = (tid & 1) * 4;      // 0 or 4
    int bRow = tid >> 5;            // 0..7
    int bCol = (tid & 31) * 4;      // 0..124

    float acc[4][4][4];
    #pragma unroll
    for (int i = 0; i < 4; i++)
        #pragma unroll
        for (int j = 0; j < 4; j++)
            #pragma unroll
            for (int r = 0; r < 4; r++) acc[i][j][r] = 0.f;

    int kIters = K / GBK;
    float4 av, bv;

    // prologue: load k-chunk 0
    {
        int gr = gm + aRow;
        av = make_float4(0.f, 0.f, 0.f, 0.f);
        if (gr < M) av = *(const float4*)(A + (size_t)gr * K + aHalf);
        bv = *(const float4*)(B + (size_t)bRow * N + gn + bCol);
    }
    // store chunk 0 into buffer 0
    {
        float ae[4] = {av.x, av.y, av.z, av.w};
        #pragma unroll
        for (int e = 0; e < 4; e++) {
            float hi = tf32_rna(ae[e]);
            sAh[0][aHalf + e][aRow] = hi;
            sAl[0][aHalf + e][aRow] = ae[e] - hi;
        }
        float4 bh, bl;
        bh.x = tf32_rna(bv.x); bl.x = bv.x - bh.x;
        bh.y = tf32_rna(bv.y); bl.y = bv.y - bh.y;
        bh.z = tf32_rna(bv.z); bl.z = bv.z - bh.z;
        bh.w = tf32_rna(bv.w); bl.w = bv.w - bh.w;
        *(float4*)&sBh[0][bRow][bCol] = bh;
        *(float4*)&sBl[0][bRow][bCol] = bl;
    }
    __syncthreads();

    for (int it = 0; it < kIters; ++it) {
        int cur = it & 1;
        // prefetch next chunk to regs
        if (it + 1 < kIters) {
            int k0 = (it + 1) * GBK;
            int gr = gm + aRow;
            av = make_float4(0.f, 0.f, 0.f, 0.f);
            if (gr < M) av = *(const float4*)(A + (size_t)gr * K + k0 + aHalf);
            bv = *(const float4*)(B + (size_t)(k0 + bRow) * N + gn + bCol);
        }
        // compute from cur buffer
        {
            float ah[4][4], al[4][4], bhf[4][2], blf[4][2];
            #pragma unroll
            for (int i = 0; i < 4; i++) {
                int m0 = warp_m + i * 16 + g;
                ah[i][0] = sAh[cur][tig][m0];
                ah[i][1] = sAh[cur][tig][m0 + 8];
                ah[i][2] = sAh[cur][tig + 4][m0];
                ah[i][3] = sAh[cur][tig + 4][m0 + 8];
                al[i][0] = sAl[cur][tig][m0];
                al[i][1] = sAl[cur][tig][m0 + 8];
                al[i][2] = sAl[cur][tig + 4][m0];
                al[i][3] = sAl[cur][tig + 4][m0 + 8];
            }
            #pragma unroll
            for (int j = 0; j < 4; j++) {
                int n0 = warp_n + j * 8 + g;
                bhf[j][0] = sBh[cur][tig][n0];
                bhf[j][1] = sBh[cur][tig + 4][n0];
                blf[j][0] = sBl[cur][tig][n0];
                blf[j][1] = sBl[cur][tig + 4][n0];
            }
            #pragma unroll
            for (int i = 0; i < 4; i++)
                #pragma unroll
                for (int j = 0; j < 4; j++) {
                    mma8(acc[i][j], al[i], bhf[j]);
                    mma8(acc[i][j], ah[i], blf[j]);
                    mma8(acc[i][j], ah[i], bhf[j]);
                }
        }
        // store next chunk to other buffer
        if (it + 1 < kIters) {
            int nxt = cur ^ 1;
            float ae[4] = {av.x, av.y, av.z, av.w};
            #pragma unroll
            for (int e = 0; e < 4; e++) {
                float hi = tf32_rna(ae[e]);
                sAh[nxt][aHalf + e][aRow] = hi;
                sAl[nxt][aHalf + e][aRow] = ae[e] - hi;
            }
            float4 bh, bl;
            bh.x = tf32_rna(bv.x); bl.x = bv.x - bh.x;
            bh.y = tf32_rna(bv.y); bl.y = bv.y - bh.y;
            bh.z = tf32_rna(bv.z); bl.z = bv.z - bh.z;
            bh.w = tf32_rna(bv.w); bl.w = bv.w - bh.w;
            *(float4*)&sBh[nxt][bRow][bCol] = bh;
            *(float4*)&sBl[nxt][bRow][bCol] = bl;
        }
        __syncthreads();
    }

    // epilogue
    #pragma unroll
    for (int i = 0; i < 4; i++) {
        int r0 = gm + warp_m + i * 16 + g;
        #pragma unroll
        for (int j = 0; j < 4; j++) {
            int c0 = gn + warp_n + j * 8 + tig * 2;
            if (r0 < M)
                *(float2*)(C + (size_t)r0 * N + c0) = make_float2(acc[i][j][0], acc[i][j][1]);
            if (r0 + 8 < M)
                *(float2*)(C + (size_t)(r0 + 8) * N + c0) = make_float2(acc[i][j][2], acc[i][j][3]);
        }
    }
}

// ---------------- per-node attention dots ----------------
__global__ void alpha1_kernel(const float* __restrict__ att_s, const float* __restrict__ att_d) {
    int w = (blockIdx.x * blockDim.x + threadIdx.x) >> 5;
    int lane = threadIdx.x & 31;
    if (w >= NN) return;
    const float4* hp = (const float4*)(g_h1 + (size_t)w * HID);
    const float4* sp = (const float4*)att_s;
    const float4* dp = (const float4*)att_d;
    float ps = 0.f, pd = 0.f;
    #pragma unroll
    for (int r = 0; r < 2; r++) {
        int i = 2 * lane + r;
        float4 v = hp[i], s = sp[i], d = dp[i];
        ps += v.x * s.x + v.y * s.y + v.z * s.z + v.w * s.w;
        pd += v.x * d.x + v.y * d.y + v.z * d.z + v.w * d.w;
    }
    #pragma unroll
    for (int off = 4; off >= 1; off >>= 1) {
        ps += __shfl_xor_sync(0xffffffffu, ps, off);
        pd += __shfl_xor_sync(0xffffffffu, pd, off);
    }
    if ((lane & 7) == 0) {
        int h = lane >> 3;
        g_as1[w * HEADS + h] = ps;
        g_ad1[w * HEADS + h] = pd;
    }
}

__global__ void alpha2_kernel(const float* __restrict__ att_s, const float* __restrict__ att_d) {
    int w = (blockIdx.x * blockDim.x + threadIdx.x) >> 5;
    int lane = threadIdx.x & 31;
    if (w >= NN) return;
    const float4* hp = (const float4*)(g_h2 + (size_t)w * OUT_DIM);
    float4 v = hp[lane];
    float4 s = ((const float4*)att_s)[lane];
    float4 d = ((const float4*)att_d)[lane];
    float ps = v.x * s.x + v.y * s.y + v.z * s.z + v.w * s.w;
    float pd = v.x * d.x + v.y * d.y + v.z * d.z + v.w * d.w;
    #pragma unroll
    for (int off = 16; off >= 1; off >>= 1) {
        ps += __shfl_xor_sync(0xffffffffu, ps, off);
        pd += __shfl_xor_sync(0xffffffffu, pd, off);
    }
    if (lane == 0) { g_as2[w] = ps; g_ad2[w] = pd; }
}

// ---------------- fused layer-1: softmax + aggregate + bias + gelu ----------------
__global__ __launch_bounds__(256) void fused_layer1(const float* __restrict__ bias1) {
    int d = (blockIdx.x * blockDim.x + threadIdx.x) >> 5;
    int lane = threadIdx.x & 31;
    if (d >= NN) return;
    int rp = g_row_ptr[d], rp1 = g_row_ptr[d + 1];
    float4 adv = *(const float4*)(g_ad1 + d * 4);

    float4 m = make_float4(NEG_INF, NEG_INF, NEG_INF, NEG_INF);
    for (int j = rp + lane; j < rp1; j += 32) {
        int s = g_csr_src[j];
        float4 av = *(const float4*)(g_as1 + s * 4);
        m.x = fmaxf(m.x, lrelu(av.x + adv.x));
        m.y = fmaxf(m.y, lrelu(av.y + adv.y));
        m.z = fmaxf(m.z, lrelu(av.z + adv.z));
        m.w = fmaxf(m.w, lrelu(av.w + adv.w));
    }
    #pragma unroll
    for (int off = 16; off >= 1; off >>= 1) {
        m.x = fmaxf(m.x, __shfl_xor_sync(0xffffffffu, m.x, off));
        m.y = fmaxf(m.y, __shfl_xor_sync(0xffffffffu, m.y, off));
        m.z = fmaxf(m.z, __shfl_xor_sync(0xffffffffu, m.z, off));
        m.w = fmaxf(m.w, __shfl_xor_sync(0xffffffffu, m.w, off));
    }

    float4 den = make_float4(0.f, 0.f, 0.f, 0.f);
    for (int j = rp + lane; j < rp1; j += 32) {
        int s = g_csr_src[j];
        float4 av = *(const float4*)(g_as1 + s * 4);
        den.x += __expf(lrelu(av.x + adv.x) - m.x);
        den.y += __expf(lrelu(av.y + adv.y) - m.y);
        den.z += __expf(lrelu(av.z + adv.z) - m.z);
        den.w += __expf(lrelu(av.w + adv.w) - m.w);
    }
    #pragma unroll
    for (int off = 16; off >= 1; off >>= 1) {
        den.x += __shfl_xor_sync(0xffffffffu, den.x, off);
        den.y += __shfl_xor_sync(0xffffffffu, den.y, off);
        den.z += __shfl_xor_sync(0xffffffffu, den.z, off);
        den.w += __shfl_xor_sync(0xffffffffu, den.w, off);
    }
    float4 inv = make_float4(1.f / (den.x + 1e-16f), 1.f / (den.y + 1e-16f),
                             1.f / (den.z + 1e-16f), 1.f / (den.w + 1e-16f));

    int hsel = (lane >> 4) & 1;
    float ma  = hsel ? m.y   : m.x,   mb  = hsel ? m.w   : m.z;
    float ia  = hsel ? inv.y : inv.x, ib  = hsel ? inv.w : inv.z;
    float ada = hsel ? adv.y : adv.x, adb = hsel ? adv.w : adv.z;

    float4 acc0 = make_float4(0.f, 0.f, 0.f, 0.f);
    float4 acc1 = make_float4(0.f, 0.f, 0.f, 0.f);
    for (int j = rp; j < rp1; j++) {
        int s = g_csr_src[j];
        float4 av = *(const float4*)(g_as1 + s * 4);
        float asa = hsel ? av.y : av.x;
        float asb = hsel ? av.w : av.z;
        float aa = __expf(lrelu(asa + ada) - ma) * ia;
        float ab = __expf(lrelu(asb + adb) - mb) * ib;
        const float4* hp = (const float4*)(g_h1 + (size_t)s * HID);
        float4 v0 = hp[lane];
        float4 v1 = hp[lane + 32];
        acc0.x += aa * v0.x; acc0.y += aa * v0.y; acc0.z += aa * v0.z; acc0.w += aa * v0.w;
        acc1.x += ab * v1.x; acc1.y += ab * v1.y; acc1.z += ab * v1.z; acc1.w += ab * v1.w;
    }

    float4 b0 = ((const float4*)bias1)[lane];
    float4 b1 = ((const float4*)bias1)[lane + 32];
    acc0.x += b0.x; acc0.y += b0.y; acc0.z += b0.z; acc0.w += b0.w;
    acc1.x += b1.x; acc1.y += b1.y; acc1.z += b1.z; acc1.w += b1.w;
    const float kI = 0.70710678118654752f;
    acc0.x = 0.5f * acc0.x * (1.f + erff(acc0.x * kI));
    acc0.y = 0.5f * acc0.y * (1.f + erff(acc0.y * kI));
    acc0.z = 0.5f * acc0.z * (1.f + erff(acc0.z * kI));
    acc0.w = 0.5f * acc0.w * (1.f + erff(acc0.w * kI));
    acc1.x = 0.5f * acc1.x * (1.f + erff(acc1.x * kI));
    acc1.y = 0.5f * acc1.y * (1.f + erff(acc1.y * kI));
    acc1.z = 0.5f * acc1.z * (1.f + erff(acc1.z * kI));
    acc1.w = 0.5f * acc1.w * (1.f + erff(acc1.w * kI));
    float4* op = (float4*)(g_out1 + (size_t)d * HID);
    op[lane] = acc0;
    op[lane + 32] = acc1;
}

// ---------------- fused layer-2: softmax + aggregate + bias -> d_out ----------------
__global__ __launch_bounds__(256) void fused_layer2(const float* __restrict__ bias2,
                                                    float* __restrict__ out) {
    int d = (blockIdx.x * blockDim.x + threadIdx.x) >> 5;
    int lane = threadIdx.x & 31;
    if (d >= NN) return;
    int rp = g_row_ptr[d], rp1 = g_row_ptr[d + 1];
    float ad = g_ad2[d];

    float m = NEG_INF;
    for (int j = rp + lane; j < rp1; j += 32)
        m = fmaxf(m, lrelu(g_as2[g_csr_src[j]] + ad));
    #pragma unroll
    for (int off = 16; off >= 1; off >>= 1)
        m = fmaxf(m, __shfl_xor_sync(0xffffffffu, m, off));

    float den = 0.f;
    for (int j = rp + lane; j < rp1; j += 32)
        den += __expf(lrelu(g_as2[g_csr_src[j]] + ad) - m);
    #pragma unroll
    for (int off = 16; off >= 1; off >>= 1)
        den += __shfl_xor_sync(0xffffffffu, den, off);
    float inv = 1.f / (den + 1e-16f);

    float4 acc = make_float4(0.f, 0.f, 0.f, 0.f);
    for (int j = rp; j < rp1; j++) {
        int s = g_csr_src[j];
        float a = __expf(lrelu(g_as2[s] + ad) - m) * inv;
        float4 v = ((const float4*)(g_h2 + (size_t)s * OUT_DIM))[lane];
        acc.x += a * v.x; acc.y += a * v.y; acc.z += a * v.z; acc.w += a * v.w;
    }
    float4 b = ((const float4*)bias2)[lane];
    acc.x += b.x; acc.y += b.y; acc.z += b.z; acc.w += b.w;
    ((float4*)(out + (size_t)d * OUT_DIM))[lane] = acc;
}

// ---------------- launch ----------------
extern "C" void kernel_launch(void* const* d_in, const int* in_sizes, int n_in,
                              void* d_out, int out_size) {
    const float* x = (const float*)d_in[0];
    const int* ei = (const int*)d_in[1];        // int32 (JAX x64 disabled)
    const float* W1 = (const float*)d_in[2];
    const float* att_src1 = (const float*)d_in[3];
    const float* att_dst1 = (const float*)d_in[4];
    const float* bias1 = (const float*)d_in[5];
    const float* W2 = (const float*)d_in[6];
    const float* att_src2 = (const float*)d_in[7];
    const float* att_dst2 = (const float*)d_in[8];
    const float* bias2 = (const float*)d_in[9];
    float* out = (float*)d_out;

    int E = in_sizes[1] / 2;
    int EL = E + NN;

    float* h1;   cudaGetSymbolAddress((void**)&h1, g_h1);
    float* out1; cudaGetSymbolAddress((void**)&out1, g_out1);
    float* h2;   cudaGetSymbolAddress((void**)&h2, g_h2);

    const int T = 256;
    // CSR build (by destination)
    init_deg<<<(NN + T - 1) / T, T>>>();
    add_deg<<<(E + T - 1) / T, T>>>(ei, E);
    scan_deg<<<1, 1024>>>(NN);
    fill_csr<<<(EL + T - 1) / T, T>>>(ei, E, EL);
    // layer 1
    {
        dim3 g(HID / GBN, (NN + GBM - 1) / GBM);
        gemm_tf32<<<g, T>>>(NN, HID, IN_DIM, x, W1, h1);
    }
    alpha1_kernel<<<(NN * 32 + T - 1) / T, T>>>(att_src1, att_dst1);
    fused_layer1<<<(NN * 32 + T - 1) / T, T>>>(bias1);
    // layer 2
    {
        dim3 g(OUT_DIM / GBN, (NN + GBM - 1) / GBM);
        gemm_tf32<<<g, T>>>(NN, OUT_DIM, HID, out1, W2, h2);
    }
    alpha2_kernel<<<(NN * 32 + T - 1) / T, T>>>(att_src2, att_dst2);
    fused_layer2<<<(NN * 32 + T - 1) / T, T>>>(bias2, out);
}

// round 10
// speedup vs baseline: 2.0270x; 1.2358x over previous
#include <cuda_runtime.h>
#include <math.h>

#define NN 50000
#define IN_DIM 256
#define HID 256
#define HEADS 4
#define OUT_DIM 128
#define NEG_SLOPE 0.2f
#define EMAXE 850000   // E + N

// ---------------- scratch (device globals) ----------------
__device__ __align__(16) float g_h1[NN * HID];       // x @ W1
__device__ __align__(16) float g_out1[NN * HID];     // layer-1 output (post-gelu)
__device__ __align__(16) float g_h2[NN * OUT_DIM];   // out1 @ W2
__device__ __align__(16) float g_as1[NN * HEADS];
__device__ __align__(16) float g_ad1[NN * HEADS];
__device__ float g_as2[NN];
__device__ float g_ad2[NN];
// CSR (by destination), rebuilt every launch
__device__ int g_deg[NN];
__device__ int g_row_ptr[NN + 1];
__device__ int g_cursor[NN];
__device__ int g_csr_src[EMAXE];

__device__ __forceinline__ float lrelu(float v) {
    return v > 0.f ? v : NEG_SLOPE * v;
}
#define NEG_INF __int_as_float(0xff800000)

// ---------------- CSR build ----------------
__global__ void init_deg() {
    int i = blockIdx.x * blockDim.x + threadIdx.x;
    if (i < NN) g_deg[i] = 1;               // self-loop pre-counted
}
__global__ void add_deg(const int* __restrict__ ei, int E) {
    int e = blockIdx.x * blockDim.x + threadIdx.x;
    if (e < E) atomicAdd(&g_deg[ei[E + e]], 1);
}
__global__ __launch_bounds__(1024) void scan_deg(int n) {
    __shared__ int warp_sums[32];
    __shared__ int s_carry;
    int tid = threadIdx.x, lane = tid & 31, wid = tid >> 5;
    if (tid == 0) s_carry = 0;
    __syncthreads();
    for (int base = 0; base < n; base += 1024) {
        int i = base + tid;
        int v = (i < n) ? g_deg[i] : 0;
        int x = v;
        #pragma unroll
        for (int off = 1; off < 32; off <<= 1) {
            int y = __shfl_up_sync(0xffffffffu, x, off);
            if (lane >= off) x += y;
        }
        if (lane == 31) warp_sums[wid] = x;
        __syncthreads();
        if (wid == 0) {
            int wv = warp_sums[lane];
            #pragma unroll
            for (int off = 1; off < 32; off <<= 1) {
                int y = __shfl_up_sync(0xffffffffu, wv, off);
                if (lane >= off) wv += y;
            }
            warp_sums[lane] = wv;
        }
        __syncthreads();
        int warp_off = (wid > 0) ? warp_sums[wid - 1] : 0;
        int incl = x + warp_off + s_carry;
        int excl = incl - v;
        if (i < n) { g_row_ptr[i] = excl; g_cursor[i] = excl; }
        __syncthreads();
        if (tid == 1023) s_carry = incl;
        __syncthreads();
    }
    if (threadIdx.x == 0) g_row_ptr[n] = s_carry;
}
__global__ void fill_csr(const int* __restrict__ ei, int E, int EL) {
    int e = blockIdx.x * blockDim.x + threadIdx.x;
    if (e >= EL) return;
    int s, d;
    if (e < E) { s = ei[e]; d = ei[E + e]; } else { s = d = e - E; }
    int pos = atomicAdd(&g_cursor[d], 1);
    g_csr_src[pos] = s;
}

// ---------------- bf16x2 helpers ----------------
// pack two fp32 -> one uint holding (bf16(e) in low half, bf16(o) in high half)
__device__ __forceinline__ unsigned bf16pack(float e, float o) {
    unsigned r;
    asm("cvt.rn.bf16x2.f32 %0, %1, %2;" : "=r"(r) : "f"(o), "f"(e));
    return r;
}
// split pair (e,o) into hi-pack and lo-pack (residual) bf16x2 words
__device__ __forceinline__ void split2(float e, float o, unsigned& hi, unsigned& lo) {
    unsigned h = bf16pack(e, o);
    float ef = __uint_as_float(h << 16);
    float of = __uint_as_float(h & 0xffff0000u);
    lo = bf16pack(e - ef, o - of);
    hi = h;
}
__device__ __forceinline__ void mma16(float* d, const unsigned* a, const unsigned* b) {
    asm volatile(
        "mma.sync.aligned.m16n8k16.row.col.f32.bf16.bf16.f32 "
        "{%0,%1,%2,%3}, {%4,%5,%6,%7}, {%8,%9}, {%0,%1,%2,%3};\n"
        : "+f"(d[0]), "+f"(d[1]), "+f"(d[2]), "+f"(d[3])
        : "r"(a[0]), "r"(a[1]), "r"(a[2]), "r"(a[3]), "r"(b[0]), "r"(b[1]));
}

// ---------------- bf16x2 tensor-core GEMM: C = A[M,K] @ B[K,N] ----------------
// block tile 128x128, BK=16, 256 threads, 8 warps (64x32 warp tiles), double-buffered.
// smem holds k-pair-packed bf16x2 words: one LDS.32 per fragment register.
#define GBM 128
#define GBN 128
#define GBK 16
#define SAU 12    // uint stride per A row   (8 k-pairs used + 4 pad) -> conflict-free frags
#define SBU 136   // uint stride per B k2row (128 n used + 8 pad)     -> conflict-free frags

__global__ __launch_bounds__(256) void gemm_bf16x2(int M, int N, int K,
                                                   const float* __restrict__ A,
                                                   const float* __restrict__ B,
                                                   float* __restrict__ C) {
    __shared__ __align__(16) unsigned sAh[2][GBM * SAU];
    __shared__ __align__(16) unsigned sAl[2][GBM * SAU];
    __shared__ __align__(16) unsigned sBh[2][(GBK / 2) * SBU];
    __shared__ __align__(16) unsigned sBl[2][(GBK / 2) * SBU];

    int tid = threadIdx.x;
    int lane = tid & 31, w = tid >> 5;
    int g = lane >> 2, tig = lane & 3;
    int warp_m = (w >> 2) * 64;     // 0 or 64
    int warp_n = (w & 3) * 32;      // 0,32,64,96
    int gm = blockIdx.y * GBM, gn = blockIdx.x * GBN;

    // staging: A: thread -> row tid>>1, 8 consecutive k ((tid&1)*8)
    int aRow = tid >> 1;
    int aK2  = (tid & 1) * 4;       // k-pair (uint) offset: 0 or 4
    // B: thread -> k-pair row tid>>5 (0..7), 4 consecutive n
    int bP = tid >> 5;
    int bN = (tid & 31) * 4;

    float acc[4][4][4];
    #pragma unroll
    for (int i = 0; i < 4; i++)
        #pragma unroll
        for (int j = 0; j < 4; j++)
            #pragma unroll
            for (int r = 0; r < 4; r++) acc[i][j][r] = 0.f;

    int kIters = K / GBK;
    float4 a0v, a1v, b0v, b1v;

    // ---- prologue: load + convert + store chunk 0 ----
    {
        int gr = gm + aRow;
        a0v = make_float4(0.f, 0.f, 0.f, 0.f); a1v = a0v;
        if (gr < M) {
            const float* ap = A + (size_t)gr * K + aK2 * 2;
            a0v = *(const float4*)ap;
            a1v = *(const float4*)(ap + 4);
        }
        const float* bp = B + (size_t)(2 * bP) * N + gn + bN;
        b0v = *(const float4*)bp;
        b1v = *(const float4*)(bp + N);
    }
    {
        unsigned h0, h1, h2, h3, l0, l1, l2, l3;
        split2(a0v.x, a0v.y, h0, l0); split2(a0v.z, a0v.w, h1, l1);
        split2(a1v.x, a1v.y, h2, l2); split2(a1v.z, a1v.w, h3, l3);
        *(uint4*)&sAh[0][aRow * SAU + aK2] = make_uint4(h0, h1, h2, h3);
        *(uint4*)&sAl[0][aRow * SAU + aK2] = make_uint4(l0, l1, l2, l3);
        split2(b0v.x, b1v.x, h0, l0); split2(b0v.y, b1v.y, h1, l1);
        split2(b0v.z, b1v.z, h2, l2); split2(b0v.w, b1v.w, h3, l3);
        *(uint4*)&sBh[0][bP * SBU + bN] = make_uint4(h0, h1, h2, h3);
        *(uint4*)&sBl[0][bP * SBU + bN] = make_uint4(l0, l1, l2, l3);
    }
    __syncthreads();

    for (int it = 0; it < kIters; ++it) {
        int cur = it & 1;
        // prefetch next chunk to regs
        if (it + 1 < kIters) {
            int k0 = (it + 1) * GBK;
            int gr = gm + aRow;
            a0v = make_float4(0.f, 0.f, 0.f, 0.f); a1v = a0v;
            if (gr < M) {
                const float* ap = A + (size_t)gr * K + k0 + aK2 * 2;
                a0v = *(const float4*)ap;
                a1v = *(const float4*)(ap + 4);
            }
            const float* bp = B + (size_t)(k0 + 2 * bP) * N + gn + bN;
            b0v = *(const float4*)bp;
            b1v = *(const float4*)(bp + N);
        }
        // ---- compute from cur buffer ----
        {
            unsigned bh[4][2], bl[4][2];
            #pragma unroll
            for (int j = 0; j < 4; j++) {
                int n0 = warp_n + j * 8 + g;
                bh[j][0] = sBh[cur][tig * SBU + n0];
                bh[j][1] = sBh[cur][(tig + 4) * SBU + n0];
                bl[j][0] = sBl[cur][tig * SBU + n0];
                bl[j][1] = sBl[cur][(tig + 4) * SBU + n0];
            }
            #pragma unroll
            for (int i = 0; i < 4; i++) {
                int m0 = warp_m + i * 16 + g;
                unsigned ah[4], al[4];
                ah[0] = sAh[cur][m0 * SAU + tig];
                ah[1] = sAh[cur][(m0 + 8) * SAU + tig];
                ah[2] = sAh[cur][m0 * SAU + tig + 4];
                ah[3] = sAh[cur][(m0 + 8) * SAU + tig + 4];
                al[0] = sAl[cur][m0 * SAU + tig];
                al[1] = sAl[cur][(m0 + 8) * SAU + tig];
                al[2] = sAl[cur][m0 * SAU + tig + 4];
                al[3] = sAl[cur][(m0 + 8) * SAU + tig + 4];
                #pragma unroll
                for (int j = 0; j < 4; j++) {
                    mma16(acc[i][j], al, bh[j]);
                    mma16(acc[i][j], ah, bl[j]);
                    mma16(acc[i][j], ah, bh[j]);
                }
            }
        }
        // ---- convert + store next chunk ----
        if (it + 1 < kIters) {
            int nxt = cur ^ 1;
            unsigned h0, h1, h2, h3, l0, l1, l2, l3;
            split2(a0v.x, a0v.y, h0, l0); split2(a0v.z, a0v.w, h1, l1);
            split2(a1v.x, a1v.y, h2, l2); split2(a1v.z, a1v.w, h3, l3);
            *(uint4*)&sAh[nxt][aRow * SAU + aK2] = make_uint4(h0, h1, h2, h3);
            *(uint4*)&sAl[nxt][aRow * SAU + aK2] = make_uint4(l0, l1, l2, l3);
            split2(b0v.x, b1v.x, h0, l0); split2(b0v.y, b1v.y, h1, l1);
            split2(b0v.z, b1v.z, h2, l2); split2(b0v.w, b1v.w, h3, l3);
            *(uint4*)&sBh[nxt][bP * SBU + bN] = make_uint4(h0, h1, h2, h3);
            *(uint4*)&sBl[nxt][bP * SBU + bN] = make_uint4(l0, l1, l2, l3);
        }
        __syncthreads();
    }

    // epilogue (same thread mapping as m16n8k8: c0,c1 -> row g col 2tig; c2,c3 -> row g+8)
    #pragma unroll
    for (int i = 0; i < 4; i++) {
        int r0 = gm + warp_m + i * 16 + g;
        #pragma unroll
        for (int j = 0; j < 4; j++) {
            int c0 = gn + warp_n + j * 8 + tig * 2;
            if (r0 < M)
                *(float2*)(C + (size_t)r0 * N + c0) = make_float2(acc[i][j][0], acc[i][j][1]);
            if (r0 + 8 < M)
                *(float2*)(C + (size_t)(r0 + 8) * N + c0) = make_float2(acc[i][j][2], acc[i][j][3]);
        }
    }
}

// ---------------- per-node attention dots ----------------
__global__ void alpha1_kernel(const float* __restrict__ att_s, const float* __restrict__ att_d) {
    int w = (blockIdx.x * blockDim.x + threadIdx.x) >> 5;
    int lane = threadIdx.x & 31;
    if (w >= NN) return;
    const float4* hp = (const float4*)(g_h1 + (size_t)w * HID);
    const float4* sp = (const float4*)att_s;
    const float4* dp = (const float4*)att_d;
    float ps = 0.f, pd = 0.f;
    #pragma unroll
    for (int r = 0; r < 2; r++) {
        int i = 2 * lane + r;
        float4 v = hp[i], s = sp[i], d = dp[i];
        ps += v.x * s.x + v.y * s.y + v.z * s.z + v.w * s.w;
        pd += v.x * d.x + v.y * d.y + v.z * d.z + v.w * d.w;
    }
    #pragma unroll
    for (int off = 4; off >= 1; off >>= 1) {
        ps += __shfl_xor_sync(0xffffffffu, ps, off);
        pd += __shfl_xor_sync(0xffffffffu, pd, off);
    }
    if ((lane & 7) == 0) {
        int h = lane >> 3;
        g_as1[w * HEADS + h] = ps;
        g_ad1[w * HEADS + h] = pd;
    }
}

__global__ void alpha2_kernel(const float* __restrict__ att_s, const float* __restrict__ att_d) {
    int w = (blockIdx.x * blockDim.x + threadIdx.x) >> 5;
    int lane = threadIdx.x & 31;
    if (w >= NN) return;
    const float4* hp = (const float4*)(g_h2 + (size_t)w * OUT_DIM);
    float4 v = hp[lane];
    float4 s = ((const float4*)att_s)[lane];
    float4 d = ((const float4*)att_d)[lane];
    float ps = v.x * s.x + v.y * s.y + v.z * s.z + v.w * s.w;
    float pd = v.x * d.x + v.y * d.y + v.z * d.z + v.w * d.w;
    #pragma unroll
    for (int off = 16; off >= 1; off >>= 1) {
        ps += __shfl_xor_sync(0xffffffffu, ps, off);
        pd += __shfl_xor_sync(0xffffffffu, pd, off);
    }
    if (lane == 0) { g_as2[w] = ps; g_ad2[w] = pd; }
}

// ---------------- fused layer-1: softmax + aggregate + bias + gelu ----------------
__global__ __launch_bounds__(256) void fused_layer1(const float* __restrict__ bias1) {
    int d = (blockIdx.x * blockDim.x + threadIdx.x) >> 5;
    int lane = threadIdx.x & 31;
    if (d >= NN) return;
    int rp = g_row_ptr[d], rp1 = g_row_ptr[d + 1];
    float4 adv = *(const float4*)(g_ad1 + d * 4);

    float4 m = make_float4(NEG_INF, NEG_INF, NEG_INF, NEG_INF);
    for (int j = rp + lane; j < rp1; j += 32) {
        int s = g_csr_src[j];
        float4 av = *(const float4*)(g_as1 + s * 4);
        m.x = fmaxf(m.x, lrelu(av.x + adv.x));
        m.y = fmaxf(m.y, lrelu(av.y + adv.y));
        m.z = fmaxf(m.z, lrelu(av.z + adv.z));
        m.w = fmaxf(m.w, lrelu(av.w + adv.w));
    }
    #pragma unroll
    for (int off = 16; off >= 1; off >>= 1) {
        m.x = fmaxf(m.x, __shfl_xor_sync(0xffffffffu, m.x, off));
        m.y = fmaxf(m.y, __shfl_xor_sync(0xffffffffu, m.y, off));
        m.z = fmaxf(m.z, __shfl_xor_sync(0xffffffffu, m.z, off));
        m.w = fmaxf(m.w, __shfl_xor_sync(0xffffffffu, m.w, off));
    }

    float4 den = make_float4(0.f, 0.f, 0.f, 0.f);
    for (int j = rp + lane; j < rp1; j += 32) {
        int s = g_csr_src[j];
        float4 av = *(const float4*)(g_as1 + s * 4);
        den.x += __expf(lrelu(av.x + adv.x) - m.x);
        den.y += __expf(lrelu(av.y + adv.y) - m.y);
        den.z += __expf(lrelu(av.z + adv.z) - m.z);
        den.w += __expf(lrelu(av.w + adv.w) - m.w);
    }
    #pragma unroll
    for (int off = 16; off >= 1; off >>= 1) {
        den.x += __shfl_xor_sync(0xffffffffu, den.x, off);
        den.y += __shfl_xor_sync(0xffffffffu, den.y, off);
        den.z += __shfl_xor_sync(0xffffffffu, den.z, off);
        den.w += __shfl_xor_sync(0xffffffffu, den.w, off);
    }
    float4 inv = make_float4(1.f / (den.x + 1e-16f), 1.f / (den.y + 1e-16f),
                             1.f / (den.z + 1e-16f), 1.f / (den.w + 1e-16f));

    int hsel = (lane >> 4) & 1;
    float ma  = hsel ? m.y   : m.x,   mb  = hsel ? m.w   : m.z;
    float ia  = hsel ? inv.y : inv.x, ib  = hsel ? inv.w : inv.z;
    float ada = hsel ? adv.y : adv.x, adb = hsel ? adv.w : adv.z;

    float4 acc0 = make_float4(0.f, 0.f, 0.f, 0.f);
    float4 acc1 = make_float4(0.f, 0.f, 0.f, 0.f);
    for (int j = rp; j < rp1; j++) {
        int s = g_csr_src[j];
        float4 av = *(const float4*)(g_as1 + s * 4);
        float asa = hsel ? av.y : av.x;
        float asb = hsel ? av.w : av.z;
        float aa = __expf(lrelu(asa + ada) - ma) * ia;
        float ab = __expf(lrelu(asb + adb) - mb) * ib;
        const float4* hp = (const float4*)(g_h1 + (size_t)s * HID);
        float4 v0 = hp[lane];
        float4 v1 = hp[lane + 32];
        acc0.x += aa * v0.x; acc0.y += aa * v0.y; acc0.z += aa * v0.z; acc0.w += aa * v0.w;
        acc1.x += ab * v1.x; acc1.y += ab * v1.y; acc1.z += ab * v1.z; acc1.w += ab * v1.w;
    }

    float4 b0 = ((const float4*)bias1)[lane];
    float4 b1 = ((const float4*)bias1)[lane + 32];
    acc0.x += b0.x; acc0.y += b0.y; acc0.z += b0.z; acc0.w += b0.w;
    acc1.x += b1.x; acc1.y += b1.y; acc1.z += b1.z; acc1.w += b1.w;
    const float kI = 0.70710678118654752f;
    acc0.x = 0.5f * acc0.x * (1.f + erff(acc0.x * kI));
    acc0.y = 0.5f * acc0.y * (1.f + erff(acc0.y * kI));
    acc0.z = 0.5f * acc0.z * (1.f + erff(acc0.z * kI));
    acc0.w = 0.5f * acc0.w * (1.f + erff(acc0.w * kI));
    acc1.x = 0.5f * acc1.x * (1.f + erff(acc1.x * kI));
    acc1.y = 0.5f * acc1.y * (1.f + erff(acc1.y * kI));
    acc1.z = 0.5f * acc1.z * (1.f + erff(acc1.z * kI));
    acc1.w = 0.5f * acc1.w * (1.f + erff(acc1.w * kI));
    float4* op = (float4*)(g_out1 + (size_t)d * HID);
    op[lane] = acc0;
    op[lane + 32] = acc1;
}

// ---------------- fused layer-2: softmax + aggregate + bias -> d_out ----------------
__global__ __launch_bounds__(256) void fused_layer2(const float* __restrict__ bias2,
                                                    float* __restrict__ out) {
    int d = (blockIdx.x * blockDim.x + threadIdx.x) >> 5;
    int lane = threadIdx.x & 31;
    if (d >= NN) return;
    int rp = g_row_ptr[d], rp1 = g_row_ptr[d + 1];
    float ad = g_ad2[d];

    float m = NEG_INF;
    for (int j = rp + lane; j < rp1; j += 32)
        m = fmaxf(m, lrelu(g_as2[g_csr_src[j]] + ad));
    #pragma unroll
    for (int off = 16; off >= 1; off >>= 1)
        m = fmaxf(m, __shfl_xor_sync(0xffffffffu, m, off));

    float den = 0.f;
    for (int j = rp + lane; j < rp1; j += 32)
        den += __expf(lrelu(g_as2[g_csr_src[j]] + ad) - m);
    #pragma unroll
    for (int off = 16; off >= 1; off >>= 1)
        den += __shfl_xor_sync(0xffffffffu, den, off);
    float inv = 1.f / (den + 1e-16f);

    float4 acc = make_float4(0.f, 0.f, 0.f, 0.f);
    for (int j = rp; j < rp1; j++) {
        int s = g_csr_src[j];
        float a = __expf(lrelu(g_as2[s] + ad) - m) * inv;
        float4 v = ((const float4*)(g_h2 + (size_t)s * OUT_DIM))[lane];
        acc.x += a * v.x; acc.y += a * v.y; acc.z += a * v.z; acc.w += a * v.w;
    }
    float4 b = ((const float4*)bias2)[lane];
    acc.x += b.x; acc.y += b.y; acc.z += b.z; acc.w += b.w;
    ((float4*)(out + (size_t)d * OUT_DIM))[lane] = acc;
}

// ---------------- launch ----------------
extern "C" void kernel_launch(void* const* d_in, const int* in_sizes, int n_in,
                              void* d_out, int out_size) {
    const float* x = (const float*)d_in[0];
    const int* ei = (const int*)d_in[1];        // int32 (JAX x64 disabled)
    const float* W1 = (const float*)d_in[2];
    const float* att_src1 = (const float*)d_in[3];
    const float* att_dst1 = (const float*)d_in[4];
    const float* bias1 = (const float*)d_in[5];
    const float* W2 = (const float*)d_in[6];
    const float* att_src2 = (const float*)d_in[7];
    const float* att_dst2 = (const float*)d_in[8];
    const float* bias2 = (const float*)d_in[9];
    float* out = (float*)d_out;

    int E = in_sizes[1] / 2;
    int EL = E + NN;

    float* h1;   cudaGetSymbolAddress((void**)&h1, g_h1);
    float* out1; cudaGetSymbolAddress((void**)&out1, g_out1);
    float* h2;   cudaGetSymbolAddress((void**)&h2, g_h2);

    const int T = 256;
    // CSR build (by destination)
    init_deg<<<(NN + T - 1) / T, T>>>();
    add_deg<<<(E + T - 1) / T, T>>>(ei, E);
    scan_deg<<<1, 1024>>>(NN);
    fill_csr<<<(EL + T - 1) / T, T>>>(ei, E, EL);
    // layer 1
    {
        dim3 g(HID / GBN, (NN + GBM - 1) / GBM);
        gemm_bf16x2<<<g, T>>>(NN, HID, IN_DIM, x, W1, h1);
    }
    alpha1_kernel<<<(NN * 32 + T - 1) / T, T>>>(att_src1, att_dst1);
    fused_layer1<<<(NN * 32 + T - 1) / T, T>>>(bias1);
    // layer 2
    {
        dim3 g(OUT_DIM / GBN, (NN + GBM - 1) / GBM);
        gemm_bf16x2<<<g, T>>>(NN, OUT_DIM, HID, out1, W2, h2);
    }
    alpha2_kernel<<<(NN * 32 + T - 1) / T, T>>>(att_src2, att_dst2);
    fused_layer2<<<(NN * 32 + T - 1) / T, T>>>(bias2, out);
}

// round 11
// speedup vs baseline: 2.1044x; 1.0382x over previous
#include <cuda_runtime.h>
#include <math.h>

#define NN 50000
#define IN_DIM 256
#define HID 256
#define HEADS 4
#define OUT_DIM 128
#define NEG_SLOPE 0.2f
#define EMAXE 850000   // E + N

// ---------------- scratch (device globals) ----------------
__device__ __align__(16) float g_h1[NN * HID];       // x @ W1
__device__ __align__(16) float g_out1[NN * HID];     // layer-1 output (post-gelu)
__device__ __align__(16) float g_h2[NN * OUT_DIM];   // out1 @ W2
__device__ __align__(16) float g_as1[NN * HEADS];
__device__ __align__(16) float g_ad1[NN * HEADS];
__device__ float g_as2[NN];
__device__ float g_ad2[NN];
// CSR (by destination), rebuilt every launch
__device__ int g_deg[NN];
__device__ int g_row_ptr[NN + 1];
__device__ int g_cursor[NN];
__device__ int g_csr_src[EMAXE];

__device__ __forceinline__ float lrelu(float v) {
    return v > 0.f ? v : NEG_SLOPE * v;
}
#define NEG_INF __int_as_float(0xff800000)

// ---------------- CSR build ----------------
__global__ void init_deg() {
    int i = blockIdx.x * blockDim.x + threadIdx.x;
    if (i < NN) g_deg[i] = 1;               // self-loop pre-counted
}
__global__ void add_deg(const int* __restrict__ ei, int E) {
    int e = blockIdx.x * blockDim.x + threadIdx.x;
    if (e < E) atomicAdd(&g_deg[ei[E + e]], 1);
}
__global__ __launch_bounds__(1024) void scan_deg(int n) {
    __shared__ int warp_sums[32];
    __shared__ int s_carry;
    int tid = threadIdx.x, lane = tid & 31, wid = tid >> 5;
    if (tid == 0) s_carry = 0;
    __syncthreads();
    for (int base = 0; base < n; base += 1024) {
        int i = base + tid;
        int v = (i < n) ? g_deg[i] : 0;
        int x = v;
        #pragma unroll
        for (int off = 1; off < 32; off <<= 1) {
            int y = __shfl_up_sync(0xffffffffu, x, off);
            if (lane >= off) x += y;
        }
        if (lane == 31) warp_sums[wid] = x;
        __syncthreads();
        if (wid == 0) {
            int wv = warp_sums[lane];
            #pragma unroll
            for (int off = 1; off < 32; off <<= 1) {
                int y = __shfl_up_sync(0xffffffffu, wv, off);
                if (lane >= off) wv += y;
            }
            warp_sums[lane] = wv;
        }
        __syncthreads();
        int warp_off = (wid > 0) ? warp_sums[wid - 1] : 0;
        int incl = x + warp_off + s_carry;
        int excl = incl - v;
        if (i < n) { g_row_ptr[i] = excl; g_cursor[i] = excl; }
        __syncthreads();
        if (tid == 1023) s_carry = incl;
        __syncthreads();
    }
    if (threadIdx.x == 0) g_row_ptr[n] = s_carry;
}
__global__ void fill_csr(const int* __restrict__ ei, int E, int EL) {
    int e = blockIdx.x * blockDim.x + threadIdx.x;
    if (e >= EL) return;
    int s, d;
    if (e < E) { s = ei[e]; d = ei[E + e]; } else { s = d = e - E; }
    int pos = atomicAdd(&g_cursor[d], 1);
    g_csr_src[pos] = s;
}

// ---------------- bf16x2 helpers ----------------
__device__ __forceinline__ unsigned bf16pack(float e, float o) {
    unsigned r;
    asm("cvt.rn.bf16x2.f32 %0, %1, %2;" : "=r"(r) : "f"(o), "f"(e));
    return r;
}
__device__ __forceinline__ void split2(float e, float o, unsigned& hi, unsigned& lo) {
    unsigned h = bf16pack(e, o);
    float ef = __uint_as_float(h << 16);
    float of = __uint_as_float(h & 0xffff0000u);
    lo = bf16pack(e - ef, o - of);
    hi = h;
}
__device__ __forceinline__ void mma16(float* d, const unsigned* a, const unsigned* b) {
    asm volatile(
        "mma.sync.aligned.m16n8k16.row.col.f32.bf16.bf16.f32 "
        "{%0,%1,%2,%3}, {%4,%5,%6,%7}, {%8,%9}, {%0,%1,%2,%3};\n"
        : "+f"(d[0]), "+f"(d[1]), "+f"(d[2]), "+f"(d[3])
        : "r"(a[0]), "r"(a[1]), "r"(a[2]), "r"(a[3]), "r"(b[0]), "r"(b[1]));
}

// ---------------- bf16x2 tensor-core GEMM + fused alpha epilogue ----------------
// C = A[M,K] @ B[K,N]; optionally alpha_s/alpha_d per-row-per-head dots with attS/attD.
// Heads are contiguous col ranges of width 2^hcLog; GBN % 2^hcLog == 0 so each head
// lies within one block (and each warp's 32-col slice within one head).
#define GBM 128
#define GBN 128
#define GBK 16
#define SAU 12
#define SBU 136

__global__ __launch_bounds__(256) void gemm_bf16x2(int M, int N, int K,
                                                   const float* __restrict__ A,
                                                   const float* __restrict__ B,
                                                   float* __restrict__ C,
                                                   const float* __restrict__ attS,
                                                   const float* __restrict__ attD,
                                                   float* __restrict__ asOut,
                                                   float* __restrict__ adOut,
                                                   int hcLog, int headsTot) {
    __shared__ __align__(16) unsigned sAh[2][GBM * SAU];
    __shared__ __align__(16) unsigned sAl[2][GBM * SAU];
    __shared__ __align__(16) unsigned sBh[2][(GBK / 2) * SBU];
    __shared__ __align__(16) unsigned sBl[2][(GBK / 2) * SBU];

    int tid = threadIdx.x;
    int lane = tid & 31, w = tid >> 5;
    int g = lane >> 2, tig = lane & 3;
    int warp_m = (w >> 2) * 64;
    int warp_n = (w & 3) * 32;
    int gm = blockIdx.y * GBM, gn = blockIdx.x * GBN;

    int aRow = tid >> 1;
    int aK2  = (tid & 1) * 4;
    int bP = tid >> 5;
    int bN = (tid & 31) * 4;

    float acc[4][4][4];
    #pragma unroll
    for (int i = 0; i < 4; i++)
        #pragma unroll
        for (int j = 0; j < 4; j++)
            #pragma unroll
            for (int r = 0; r < 4; r++) acc[i][j][r] = 0.f;

    int kIters = K / GBK;
    float4 a0v, a1v, b0v, b1v;

    {
        int gr = gm + aRow;
        a0v = make_float4(0.f, 0.f, 0.f, 0.f); a1v = a0v;
        if (gr < M) {
            const float* ap = A + (size_t)gr * K + aK2 * 2;
            a0v = *(const float4*)ap;
            a1v = *(const float4*)(ap + 4);
        }
        const float* bp = B + (size_t)(2 * bP) * N + gn + bN;
        b0v = *(const float4*)bp;
        b1v = *(const float4*)(bp + N);
    }
    {
        unsigned h0, h1, h2, h3, l0, l1, l2, l3;
        split2(a0v.x, a0v.y, h0, l0); split2(a0v.z, a0v.w, h1, l1);
        split2(a1v.x, a1v.y, h2, l2); split2(a1v.z, a1v.w, h3, l3);
        *(uint4*)&sAh[0][aRow * SAU + aK2] = make_uint4(h0, h1, h2, h3);
        *(uint4*)&sAl[0][aRow * SAU + aK2] = make_uint4(l0, l1, l2, l3);
        split2(b0v.x, b1v.x, h0, l0); split2(b0v.y, b1v.y, h1, l1);
        split2(b0v.z, b1v.z, h2, l2); split2(b0v.w, b1v.w, h3, l3);
        *(uint4*)&sBh[0][bP * SBU + bN] = make_uint4(h0, h1, h2, h3);
        *(uint4*)&sBl[0][bP * SBU + bN] = make_uint4(l0, l1, l2, l3);
    }
    __syncthreads();

    for (int it = 0; it < kIters; ++it) {
        int cur = it & 1;
        if (it + 1 < kIters) {
            int k0 = (it + 1) * GBK;
            int gr = gm + aRow;
            a0v = make_float4(0.f, 0.f, 0.f, 0.f); a1v = a0v;
            if (gr < M) {
                const float* ap = A + (size_t)gr * K + k0 + aK2 * 2;
                a0v = *(const float4*)ap;
                a1v = *(const float4*)(ap + 4);
            }
            const float* bp = B + (size_t)(k0 + 2 * bP) * N + gn + bN;
            b0v = *(const float4*)bp;
            b1v = *(const float4*)(bp + N);
        }
        {
            unsigned bh[4][2], bl[4][2];
            #pragma unroll
            for (int j = 0; j < 4; j++) {
                int n0 = warp_n + j * 8 + g;
                bh[j][0] = sBh[cur][tig * SBU + n0];
                bh[j][1] = sBh[cur][(tig + 4) * SBU + n0];
                bl[j][0] = sBl[cur][tig * SBU + n0];
                bl[j][1] = sBl[cur][(tig + 4) * SBU + n0];
            }
            #pragma unroll
            for (int i = 0; i < 4; i++) {
                int m0 = warp_m + i * 16 + g;
                unsigned ah[4], al[4];
                ah[0] = sAh[cur][m0 * SAU + tig];
                ah[1] = sAh[cur][(m0 + 8) * SAU + tig];
                ah[2] = sAh[cur][m0 * SAU + tig + 4];
                ah[3] = sAh[cur][(m0 + 8) * SAU + tig + 4];
                al[0] = sAl[cur][m0 * SAU + tig];
                al[1] = sAl[cur][(m0 + 8) * SAU + tig];
                al[2] = sAl[cur][m0 * SAU + tig + 4];
                al[3] = sAl[cur][(m0 + 8) * SAU + tig + 4];
                #pragma unroll
                for (int j = 0; j < 4; j++) {
                    mma16(acc[i][j], al, bh[j]);
                    mma16(acc[i][j], ah, bl[j]);
                    mma16(acc[i][j], ah, bh[j]);
                }
            }
        }
        if (it + 1 < kIters) {
            int nxt = cur ^ 1;
            unsigned h0, h1, h2, h3, l0, l1, l2, l3;
            split2(a0v.x, a0v.y, h0, l0); split2(a0v.z, a0v.w, h1, l1);
            split2(a1v.x, a1v.y, h2, l2); split2(a1v.z, a1v.w, h3, l3);
            *(uint4*)&sAh[nxt][aRow * SAU + aK2] = make_uint4(h0, h1, h2, h3);
            *(uint4*)&sAl[nxt][aRow * SAU + aK2] = make_uint4(l0, l1, l2, l3);
            split2(b0v.x, b1v.x, h0, l0); split2(b0v.y, b1v.y, h1, l1);
            split2(b0v.z, b1v.z, h2, l2); split2(b0v.w, b1v.w, h3, l3);
            *(uint4*)&sBh[nxt][bP * SBU + bN] = make_uint4(h0, h1, h2, h3);
            *(uint4*)&sBl[nxt][bP * SBU + bN] = make_uint4(l0, l1, l2, l3);
        }
        __syncthreads();
    }

    // C epilogue
    #pragma unroll
    for (int i = 0; i < 4; i++) {
        int r0 = gm + warp_m + i * 16 + g;
        #pragma unroll
        for (int j = 0; j < 4; j++) {
            int c0 = gn + warp_n + j * 8 + tig * 2;
            if (r0 < M)
                *(float2*)(C + (size_t)r0 * N + c0) = make_float2(acc[i][j][0], acc[i][j][1]);
            if (r0 + 8 < M)
                *(float2*)(C + (size_t)(r0 + 8) * N + c0) = make_float2(acc[i][j][2], acc[i][j][3]);
        }
    }

    // alpha epilogue: per-row, per-head dots with attS/attD from fp32 accumulators
    if (attS != nullptr) {
        float* sd = (float*)sAh;     // [128 rows][2 heads-local][2 (s,d)] = 512 floats
        for (int t = tid; t < GBM * 2 * 2; t += 256) sd[t] = 0.f;
        __syncthreads();
        int hl = warp_n >> hcLog;    // head-local index of this warp's 32-col slice
        float as0[4], as1[4], ad0[4], ad1[4];
        #pragma unroll
        for (int j = 0; j < 4; j++) {
            int c = gn + warp_n + j * 8 + tig * 2;
            as0[j] = attS[c]; as1[j] = attS[c + 1];
            ad0[j] = attD[c]; ad1[j] = attD[c + 1];
        }
        #pragma unroll
        for (int i = 0; i < 4; i++) {
            float psA = 0.f, pdA = 0.f, psB = 0.f, pdB = 0.f;
            #pragma unroll
            for (int j = 0; j < 4; j++) {
                psA += acc[i][j][0] * as0[j] + acc[i][j][1] * as1[j];
                pdA += acc[i][j][0] * ad0[j] + acc[i][j][1] * ad1[j];
                psB += acc[i][j][2] * as0[j] + acc[i][j][3] * as1[j];
                pdB += acc[i][j][2] * ad0[j] + acc[i][j][3] * ad1[j];
            }
            #pragma unroll
            for (int off = 1; off <= 2; off <<= 1) {
                psA += __shfl_xor_sync(0xffffffffu, psA, off);
                pdA += __shfl_xor_sync(0xffffffffu, pdA, off);
                psB += __shfl_xor_sync(0xffffffffu, psB, off);
                pdB += __shfl_xor_sync(0xffffffffu, pdB, off);
            }
            if (tig == 0) {
                int rA = warp_m + i * 16 + g;
                int rB = rA + 8;
                atomicAdd(&sd[(rA * 2 + hl) * 2 + 0], psA);
                atomicAdd(&sd[(rA * 2 + hl) * 2 + 1], pdA);
                atomicAdd(&sd[(rB * 2 + hl) * 2 + 0], psB);
                atomicAdd(&sd[(rB * 2 + hl) * 2 + 1], pdB);
            }
        }
        __syncthreads();
        if (tid < GBM) {
            int grow = gm + tid;
            if (grow < M) {
                int hpb = GBN >> hcLog;          // heads per block (2 or 1)
                int hbase = gn >> hcLog;
                for (int h = 0; h < hpb; h++) {
                    asOut[(size_t)grow * headsTot + hbase + h] = sd[(tid * 2 + h) * 2 + 0];
                    adOut[(size_t)grow * headsTot + hbase + h] = sd[(tid * 2 + h) * 2 + 1];
                }
            }
        }
    }
}

// ---------------- fused layer-1: softmax + aggregate + bias + gelu ----------------
__global__ __launch_bounds__(256) void fused_layer1(const float* __restrict__ bias1) {
    int d = (blockIdx.x * blockDim.x + threadIdx.x) >> 5;
    int lane = threadIdx.x & 31;
    if (d >= NN) return;
    int rp = g_row_ptr[d], rp1 = g_row_ptr[d + 1];
    float4 adv = *(const float4*)(g_ad1 + d * 4);

    float4 m = make_float4(NEG_INF, NEG_INF, NEG_INF, NEG_INF);
    for (int j = rp + lane; j < rp1; j += 32) {
        int s = g_csr_src[j];
        float4 av = *(const float4*)(g_as1 + s * 4);
        m.x = fmaxf(m.x, lrelu(av.x + adv.x));
        m.y = fmaxf(m.y, lrelu(av.y + adv.y));
        m.z = fmaxf(m.z, lrelu(av.z + adv.z));
        m.w = fmaxf(m.w, lrelu(av.w + adv.w));
    }
    #pragma unroll
    for (int off = 16; off >= 1; off >>= 1) {
        m.x = fmaxf(m.x, __shfl_xor_sync(0xffffffffu, m.x, off));
        m.y = fmaxf(m.y, __shfl_xor_sync(0xffffffffu, m.y, off));
        m.z = fmaxf(m.z, __shfl_xor_sync(0xffffffffu, m.z, off));
        m.w = fmaxf(m.w, __shfl_xor_sync(0xffffffffu, m.w, off));
    }

    float4 den = make_float4(0.f, 0.f, 0.f, 0.f);
    for (int j = rp + lane; j < rp1; j += 32) {
        int s = g_csr_src[j];
        float4 av = *(const float4*)(g_as1 + s * 4);
        den.x += __expf(lrelu(av.x + adv.x) - m.x);
        den.y += __expf(lrelu(av.y + adv.y) - m.y);
        den.z += __expf(lrelu(av.z + adv.z) - m.z);
        den.w += __expf(lrelu(av.w + adv.w) - m.w);
    }
    #pragma unroll
    for (int off = 16; off >= 1; off >>= 1) {
        den.x += __shfl_xor_sync(0xffffffffu, den.x, off);
        den.y += __shfl_xor_sync(0xffffffffu, den.y, off);
        den.z += __shfl_xor_sync(0xffffffffu, den.z, off);
        den.w += __shfl_xor_sync(0xffffffffu, den.w, off);
    }
    float4 inv = make_float4(1.f / (den.x + 1e-16f), 1.f / (den.y + 1e-16f),
                             1.f / (den.z + 1e-16f), 1.f / (den.w + 1e-16f));

    int hsel = (lane >> 4) & 1;
    float ma  = hsel ? m.y   : m.x,   mb  = hsel ? m.w   : m.z;
    float ia  = hsel ? inv.y : inv.x, ib  = hsel ? inv.w : inv.z;
    float ada = hsel ? adv.y : adv.x, adb = hsel ? adv.w : adv.z;

    float4 acc0 = make_float4(0.f, 0.f, 0.f, 0.f);
    float4 acc1 = make_float4(0.f, 0.f, 0.f, 0.f);
    for (int j = rp; j < rp1; j++) {
        int s = g_csr_src[j];
        float4 av = *(const float4*)(g_as1 + s * 4);
        float asa = hsel ? av.y : av.x;
        float asb = hsel ? av.w : av.z;
        float aa = __expf(lrelu(asa + ada) - ma) * ia;
        float ab = __expf(lrelu(asb + adb) - mb) * ib;
        const float4* hp = (const float4*)(g_h1 + (size_t)s * HID);
        float4 v0 = hp[lane];
        float4 v1 = hp[lane + 32];
        acc0.x += aa * v0.x; acc0.y += aa * v0.y; acc0.z += aa * v0.z; acc0.w += aa * v0.w;
        acc1.x += ab * v1.x; acc1.y += ab * v1.y; acc1.z += ab * v1.z; acc1.w += ab * v1.w;
    }

    float4 b0 = ((const float4*)bias1)[lane];
    float4 b1 = ((const float4*)bias1)[lane + 32];
    acc0.x += b0.x; acc0.y += b0.y; acc0.z += b0.z; acc0.w += b0.w;
    acc1.x += b1.x; acc1.y += b1.y; acc1.z += b1.z; acc1.w += b1.w;
    const float kI = 0.70710678118654752f;
    acc0.x = 0.5f * acc0.x * (1.f + erff(acc0.x * kI));
    acc0.y = 0.5f * acc0.y * (1.f + erff(acc0.y * kI));
    acc0.z = 0.5f * acc0.z * (1.f + erff(acc0.z * kI));
    acc0.w = 0.5f * acc0.w * (1.f + erff(acc0.w * kI));
    acc1.x = 0.5f * acc1.x * (1.f + erff(acc1.x * kI));
    acc1.y = 0.5f * acc1.y * (1.f + erff(acc1.y * kI));
    acc1.z = 0.5f * acc1.z * (1.f + erff(acc1.z * kI));
    acc1.w = 0.5f * acc1.w * (1.f + erff(acc1.w * kI));
    float4* op = (float4*)(g_out1 + (size_t)d * HID);
    op[lane] = acc0;
    op[lane + 32] = acc1;
}

// ---------------- fused layer-2: softmax + aggregate + bias -> d_out ----------------
__global__ __launch_bounds__(256) void fused_layer2(const float* __restrict__ bias2,
                                                    float* __restrict__ out) {
    int d = (blockIdx.x * blockDim.x + threadIdx.x) >> 5;
    int lane = threadIdx.x & 31;
    if (d >= NN) return;
    int rp = g_row_ptr[d], rp1 = g_row_ptr[d + 1];
    float ad = g_ad2[d];

    float m = NEG_INF;
    for (int j = rp + lane; j < rp1; j += 32)
        m = fmaxf(m, lrelu(g_as2[g_csr_src[j]] + ad));
    #pragma unroll
    for (int off = 16; off >= 1; off >>= 1)
        m = fmaxf(m, __shfl_xor_sync(0xffffffffu, m, off));

    float den = 0.f;
    for (int j = rp + lane; j < rp1; j += 32)
        den += __expf(lrelu(g_as2[g_csr_src[j]] + ad) - m);
    #pragma unroll
    for (int off = 16; off >= 1; off >>= 1)
        den += __shfl_xor_sync(0xffffffffu, den, off);
    float inv = 1.f / (den + 1e-16f);

    float4 acc = make_float4(0.f, 0.f, 0.f, 0.f);
    for (int j = rp; j < rp1; j++) {
        int s = g_csr_src[j];
        float a = __expf(lrelu(g_as2[s] + ad) - m) * inv;
        float4 v = ((const float4*)(g_h2 + (size_t)s * OUT_DIM))[lane];
        acc.x += a * v.x; acc.y += a * v.y; acc.z += a * v.z; acc.w += a * v.w;
    }
    float4 b = ((const float4*)bias2)[lane];
    acc.x += b.x; acc.y += b.y; acc.z += b.z; acc.w += b.w;
    ((float4*)(out + (size_t)d * OUT_DIM))[lane] = acc;
}

// ---------------- launch ----------------
extern "C" void kernel_launch(void* const* d_in, const int* in_sizes, int n_in,
                              void* d_out, int out_size) {
    const float* x = (const float*)d_in[0];
    const int* ei = (const int*)d_in[1];        // int32 (JAX x64 disabled)
    const float* W1 = (const float*)d_in[2];
    const float* att_src1 = (const float*)d_in[3];
    const float* att_dst1 = (const float*)d_in[4];
    const float* bias1 = (const float*)d_in[5];
    const float* W2 = (const float*)d_in[6];
    const float* att_src2 = (const float*)d_in[7];
    const float* att_dst2 = (const float*)d_in[8];
    const float* bias2 = (const float*)d_in[9];
    float* out = (float*)d_out;

    int E = in_sizes[1] / 2;
    int EL = E + NN;

    float* h1;   cudaGetSymbolAddress((void**)&h1, g_h1);
    float* out1; cudaGetSymbolAddress((void**)&out1, g_out1);
    float* h2;   cudaGetSymbolAddress((void**)&h2, g_h2);
    float* as1;  cudaGetSymbolAddress((void**)&as1, g_as1);
    float* ad1;  cudaGetSymbolAddress((void**)&ad1, g_ad1);
    float* as2;  cudaGetSymbolAddress((void**)&as2, g_as2);
    float* ad2;  cudaGetSymbolAddress((void**)&ad2, g_ad2);

    // one-time side stream + events (host resources only; identical work per call)
    static cudaStream_t s2 = nullptr;
    static cudaEvent_t evFork = nullptr, evJoin = nullptr;
    if (s2 == nullptr) {
        cudaStreamCreateWithFlags(&s2, cudaStreamNonBlocking);
        cudaEventCreateWithFlags(&evFork, cudaEventDisableTiming);
        cudaEventCreateWithFlags(&evJoin, cudaEventDisableTiming);
    }

    const int T = 256;

    // fork: CSR build chain on s2, concurrent with GEMM1 on the main stream
    cudaEventRecord(evFork, 0);
    cudaStreamWaitEvent(s2, evFork, 0);
    init_deg<<<(NN + T - 1) / T, T, 0, s2>>>();
    add_deg<<<(E + T - 1) / T, T, 0, s2>>>(ei, E);
    scan_deg<<<1, 1024, 0, s2>>>(NN);
    fill_csr<<<(EL + T - 1) / T, T, 0, s2>>>(ei, E, EL);
    cudaEventRecord(evJoin, s2);

    // main: h1 = x @ W1 with fused alpha1 (heads of width 64, 4 total)
    {
        dim3 g(HID / GBN, (NN + GBM - 1) / GBM);
        gemm_bf16x2<<<g, T>>>(NN, HID, IN_DIM, x, W1, h1,
                              att_src1, att_dst1, as1, ad1, 6, HEADS);
    }

    // join CSR before the edge phase
    cudaStreamWaitEvent(0, evJoin, 0);
    fused_layer1<<<(NN * 32 + T - 1) / T, T>>>(bias1);

    // h2 = out1 @ W2 with fused alpha2 (single head of width 128)
    {
        dim3 g(OUT_DIM / GBN, (NN + GBM - 1) / GBM);
        gemm_bf16x2<<<g, T>>>(NN, OUT_DIM, HID, out1, W2, h2,
                              att_src2, att_dst2, as2, ad2, 7, 1);
    }
    fused_layer2<<<(NN * 32 + T - 1) / T, T>>>(bias2, out);
}